// round 1
// baseline (speedup 1.0000x reference)
#include <cuda_runtime.h>
#include <math.h>

#define NA 80000
#define NE 250000
#define NG 2000
#define DD 256
#define APG 40  // atoms per graph (80000/2000)

// ---------------- scratch (device globals; no allocation allowed) ------------
__device__ float g_Ah[NA * DD];     // A(h)
__device__ float g_Eh[NA * DD];     // E(h)
__device__ float g_Cu[NG * DD];     // C(u)
__device__ float g_Fu[NG * DD];     // F(u)
__device__ float g_Iu[NG * DD];     // I(u)
__device__ float g_num[NA * DD];    // gated numerator
__device__ float g_den[NA * DD];    // gated denominator
__device__ float g_Gh[NA * DD];     // G(h2)
__device__ float g_HeA[NA * DD];    // per-atom sum of H(e2) over incoming edges
__device__ float g_deg[NA];         // per-atom in-degree
__device__ double g_sum[DD];        // BN column sum
__device__ double g_sumsq[DD];      // BN column sum of squares

// ---------------- zero kernels ----------------------------------------------
__global__ void kzero_stage2() {
    size_t i = (size_t)blockIdx.x * blockDim.x + threadIdx.x;
    size_t n = (size_t)NA * DD;
    for (; i < n; i += (size_t)gridDim.x * blockDim.x) { g_num[i] = 0.f; g_den[i] = 0.f; }
}
__global__ void kzero_stage3() {
    size_t i = (size_t)blockIdx.x * blockDim.x + threadIdx.x;
    size_t n = (size_t)NA * DD;
    for (; i < n; i += (size_t)gridDim.x * blockDim.x) {
        g_HeA[i] = 0.f;
        if (i < NA) g_deg[i] = 0.f;
    }
}
__global__ void kzero_stats() {
    int i = threadIdx.x;
    g_sum[i] = 0.0; g_sumsq[i] = 0.0;
}

// ---------------- SGEMM: C = A @ W + b  (K = N = 256 fixed) -----------------
// 64x64 block tile, 256 threads, 4x4 microtile.
// If sidx != nullptr, atomically scatters each output row into C[sidx[row]].
__global__ void __launch_bounds__(256) sgemm_bias(
    const float* __restrict__ A, const float* __restrict__ W,
    const float* __restrict__ bias, float* __restrict__ C, int M,
    const int* __restrict__ sidx)
{
    __shared__ __align__(16) float As[16][68];  // As[k][m]
    __shared__ __align__(16) float Bs[16][68];  // Bs[k][n]
    const int tid = threadIdx.x;
    const int tm = tid >> 4;   // 0..15
    const int tn = tid & 15;   // 0..15
    const int row0 = blockIdx.x * 64;
    const int col0 = blockIdx.y * 64;

    float acc[4][4];
#pragma unroll
    for (int i = 0; i < 4; i++)
#pragma unroll
        for (int j = 0; j < 4; j++) acc[i][j] = 0.f;

    for (int k0 = 0; k0 < 256; k0 += 16) {
#pragma unroll
        for (int i = 0; i < 4; i++) {
            int lin = tid + 256 * i;
            int r = lin >> 4, c = lin & 15;
            int row = row0 + r;
            As[c][r] = (row < M) ? A[(size_t)row * 256 + k0 + c] : 0.f;
        }
#pragma unroll
        for (int i = 0; i < 4; i++) {
            int lin = tid + 256 * i;
            int kk = lin >> 6, n = lin & 63;
            Bs[kk][n] = W[(size_t)(k0 + kk) * 256 + col0 + n];
        }
        __syncthreads();
#pragma unroll
        for (int kk = 0; kk < 16; kk++) {
            float4 a4 = *reinterpret_cast<const float4*>(&As[kk][tm * 4]);
            float4 b4 = *reinterpret_cast<const float4*>(&Bs[kk][tn * 4]);
            float a[4] = {a4.x, a4.y, a4.z, a4.w};
            float bv[4] = {b4.x, b4.y, b4.z, b4.w};
#pragma unroll
            for (int i = 0; i < 4; i++)
#pragma unroll
                for (int j = 0; j < 4; j++) acc[i][j] += a[i] * bv[j];
        }
        __syncthreads();
    }

#pragma unroll
    for (int i = 0; i < 4; i++) {
        int row = row0 + tm * 4 + i;
        if (row >= M) continue;
        if (sidx) {
            int drow = sidx[row];
#pragma unroll
            for (int j = 0; j < 4; j++) {
                int col = col0 + tn * 4 + j;
                atomicAdd(&C[(size_t)drow * 256 + col], acc[i][j] + bias[col]);
            }
        } else {
#pragma unroll
            for (int j = 0; j < 4; j++) {
                int col = col0 + tn * 4 + j;
                C[(size_t)row * 256 + col] = acc[i][j] + bias[col];
            }
        }
    }
}

// ---------------- stage 1: edge assemble ------------------------------------
// epre (already holds Be) += Ah[src] + Ah[dst] + Cu[gid[src]]
__global__ void edge_assemble(float* __restrict__ epre, const int* __restrict__ src,
                              const int* __restrict__ dst, const int* __restrict__ gid)
{
    int e = blockIdx.x;
    int c = threadIdx.x;
    int s = src[e], d = dst[e];
    int g = gid[s];
    epre[(size_t)e * 256 + c] += g_Ah[(size_t)s * 256 + c] + g_Ah[(size_t)d * 256 + c] +
                                 g_Cu[(size_t)g * 256 + c];
}

// ---------------- BatchNorm stats + apply -----------------------------------
__global__ void bn_stats(const float* __restrict__ X, int M)
{
    const int ROWS = 256;
    int c = threadIdx.x;
    int r0 = blockIdx.x * ROWS;
    int r1 = min(r0 + ROWS, M);
    float s = 0.f, s2 = 0.f;
    for (int r = r0; r < r1; r++) {
        float v = X[(size_t)r * 256 + c];
        s += v; s2 += v * v;
    }
    atomicAdd(&g_sum[c], (double)s);
    atomicAdd(&g_sumsq[c], (double)s2);
}

__global__ void bn_apply_relu(float* __restrict__ X, int M,
                              const float* __restrict__ gam, const float* __restrict__ bet)
{
    int c = threadIdx.x;
    double mean = g_sum[c] / M;
    double var = g_sumsq[c] / M - mean * mean;
    float scale = gam[c] * rsqrtf((float)(var + 1e-5));
    float mu = (float)mean;
    float bb = bet[c];
    for (int r = blockIdx.x; r < M; r += gridDim.x) {
        float v = (X[(size_t)r * 256 + c] - mu) * scale + bb;
        X[(size_t)r * 256 + c] = v > 0.f ? v : 0.f;
    }
}

// ---------------- stage 2: gated neighbor aggregation ------------------------
__global__ void edge_scatter(const float* __restrict__ e2, const int* __restrict__ src,
                             const int* __restrict__ dst)
{
    int e = blockIdx.x;
    int c = threadIdx.x;
    int s = src[e], d = dst[e];
    float x = e2[(size_t)e * 256 + c];
    float sg = 1.f / (1.f + __expf(-x));
    atomicAdd(&g_num[(size_t)d * 256 + c], sg * g_Eh[(size_t)s * 256 + c]);
    atomicAdd(&g_den[(size_t)d * 256 + c], sg);
}

__global__ void h2_assemble(float* __restrict__ h2, const int* __restrict__ gid)
{
    int a = blockIdx.x;
    int c = threadIdx.x;
    int g = gid[a];
    size_t idx = (size_t)a * 256 + c;
    h2[idx] += g_num[idx] / (g_den[idx] + 1e-6f) + g_Fu[(size_t)g * 256 + c];
}

// ---------------- stage 3: global update ------------------------------------
__global__ void deg_count(const int* __restrict__ dst)
{
    int e = blockIdx.x * blockDim.x + threadIdx.x;
    if (e < NE) atomicAdd(&g_deg[dst[e]], 1.f);
}

__global__ void graph_reduce(float* __restrict__ u2)
{
    int g = blockIdx.x;
    int c = threadIdx.x;
    int a0 = g * APG;
    float gh = 0.f, he = 0.f;
    for (int a = a0; a < a0 + APG; a++) {
        gh += g_Gh[(size_t)a * 256 + c];
        he += g_HeA[(size_t)a * 256 + c];
    }
    __shared__ float sdeg;
    if (c == 0) {
        float dsum = 0.f;
        for (int a = a0; a < a0 + APG; a++) dsum += g_deg[a];
        sdeg = dsum;
    }
    __syncthreads();
    u2[(size_t)g * 256 + c] = gh * (1.f / APG) + he / sdeg + g_Iu[(size_t)g * 256 + c];
}

// ---------------- launch ------------------------------------------------------
extern "C" void kernel_launch(void* const* d_in, const int* in_sizes, int n_in,
                              void* d_out, int out_size)
{
    const float* h     = (const float*)d_in[0];
    const float* e     = (const float*)d_in[1];
    const float* u     = (const float*)d_in[2];
    const float* W     = (const float*)d_in[3];
    const float* b     = (const float*)d_in[4];
    const float* gamma = (const float*)d_in[5];
    const float* beta  = (const float*)d_in[6];
    const int*   src   = (const int*)d_in[7];
    const int*   dst   = (const int*)d_in[8];
    const int*   gid   = (const int*)d_in[9];

    float* out_h2 = (float*)d_out;
    float* out_e2 = out_h2 + (size_t)NA * DD;
    float* out_u2 = out_e2 + (size_t)NE * DD;

    float *pAh, *pEh, *pCu, *pFu, *pIu, *pGh, *pHeA;
    cudaGetSymbolAddress((void**)&pAh, g_Ah);
    cudaGetSymbolAddress((void**)&pEh, g_Eh);
    cudaGetSymbolAddress((void**)&pCu, g_Cu);
    cudaGetSymbolAddress((void**)&pFu, g_Fu);
    cudaGetSymbolAddress((void**)&pIu, g_Iu);
    cudaGetSymbolAddress((void**)&pGh, g_Gh);
    cudaGetSymbolAddress((void**)&pHeA, g_HeA);

    const float* W0 = W + 0 * 65536; const float* b0 = b + 0 * 256;
    const float* W1 = W + 1 * 65536; const float* b1 = b + 1 * 256;
    const float* W2 = W + 2 * 65536; const float* b2 = b + 2 * 256;
    const float* W3 = W + 3 * 65536; const float* b3 = b + 3 * 256;
    const float* W4 = W + 4 * 65536; const float* b4 = b + 4 * 256;
    const float* W5 = W + 5 * 65536; const float* b5 = b + 5 * 256;
    const float* W6 = W + 6 * 65536; const float* b6 = b + 6 * 256;
    const float* W7 = W + 7 * 65536; const float* b7 = b + 7 * 256;
    const float* W8 = W + 8 * 65536; const float* b8 = b + 8 * 256;

    dim3 blk(256);
    dim3 gA((NA + 63) / 64, 4);
    dim3 gE((NE + 63) / 64, 4);
    dim3 gU((NG + 63) / 64, 4);

    // ---- stage 1: edge update ----
    sgemm_bias<<<gA, blk>>>(h, W0, b0, pAh, NA, nullptr);        // Ah
    sgemm_bias<<<gE, blk>>>(e, W1, b1, out_e2, NE, nullptr);     // Be -> e2 staging
    sgemm_bias<<<gU, blk>>>(u, W2, b2, pCu, NG, nullptr);        // Cu
    edge_assemble<<<NE, 256>>>(out_e2, src, dst, gid);
    kzero_stats<<<1, 256>>>();
    bn_stats<<<(NE + 255) / 256, 256>>>(out_e2, NE);
    bn_apply_relu<<<4096, 256>>>(out_e2, NE, gamma + DD, beta + DD);   // gamma[1]

    // ---- stage 2: atom update ----
    kzero_stage2<<<2048, 256>>>();
    sgemm_bias<<<gA, blk>>>(h, W4, b4, pEh, NA, nullptr);        // Eh
    sgemm_bias<<<gA, blk>>>(h, W3, b3, out_h2, NA, nullptr);     // Dh -> h2 staging
    sgemm_bias<<<gU, blk>>>(u, W5, b5, pFu, NG, nullptr);        // Fu
    edge_scatter<<<NE, 256>>>(out_e2, src, dst);
    h2_assemble<<<NA, 256>>>(out_h2, gid);
    kzero_stats<<<1, 256>>>();
    bn_stats<<<(NA + 255) / 256, 256>>>(out_h2, NA);
    bn_apply_relu<<<4096, 256>>>(out_h2, NA, gamma, beta);             // gamma[0]

    // ---- stage 3: global update ----
    kzero_stage3<<<2048, 256>>>();
    sgemm_bias<<<gA, blk>>>(out_h2, W6, b6, pGh, NA, nullptr);   // Gh
    sgemm_bias<<<gE, blk>>>(out_e2, W7, b7, pHeA, NE, dst);      // He scattered to dst atom
    sgemm_bias<<<gU, blk>>>(u, W8, b8, pIu, NG, nullptr);        // Iu
    deg_count<<<(NE + 255) / 256, 256>>>(dst);
    graph_reduce<<<NG, 256>>>(out_u2);
    kzero_stats<<<1, 256>>>();
    bn_stats<<<(NG + 255) / 256, 256>>>(out_u2, NG);
    bn_apply_relu<<<2000, 256>>>(out_u2, NG, gamma + 2 * DD, beta + 2 * DD);  // gamma[2]
}

// round 3
// speedup vs baseline: 1.9586x; 1.9586x over previous
#include <cuda_runtime.h>
#include <cstdint>
#include <math.h>

#define NA 80000
#define NE 250000
#define NG 2000
#define APG 40

// ---------------- device scratch (no allocation allowed) ---------------------
__device__ float g_Ah[NA * 256];
__device__ float g_Eh[NA * 256];
__device__ float g_Cu[NG * 256];
__device__ float g_Fu[NG * 256];
__device__ float g_Iu[NG * 256];
__device__ float g_num[NA * 256];
__device__ float g_den[NA * 256];
__device__ float g_Gh[NA * 256];
__device__ float g_HeA[NA * 256];
__device__ float g_deg[NA];
__device__ float g_Wt[9 * 256 * 256];   // transposed weights [i][n][k]
__device__ double g_sum[256];
__device__ double g_sumsq[256];

__device__ __forceinline__ uint32_t f2tf32(float v) {
    uint32_t u;
    asm("cvt.rna.tf32.f32 %0, %1;" : "=r"(u) : "f"(v));
    return u;
}
__device__ __forceinline__ void red_add_v4(float* addr, float a, float b, float c, float d) {
    asm volatile("red.global.add.v4.f32 [%0], {%1, %2, %3, %4};"
        :: "l"(addr), "f"(a), "f"(b), "f"(c), "f"(d) : "memory");
}
__device__ __forceinline__ void red_add_v2(float* addr, float a, float b) {
    asm volatile("red.global.add.v2.f32 [%0], {%1, %2};"
        :: "l"(addr), "f"(a), "f"(b) : "memory");
}

// ---------------- tf32 mma.sync GEMM: C[M,256] = A[M,256] @ W + b -----------
// CTA tile 128x128 (grid.y = 2 halves of N=256). 8 warps, warp tile 64x32.
// Wt rows are K-major (Wt[n][k]); fragments loaded directly from padded smem.
// If sidx != nullptr, rows are scatter-added into C[sidx[row]] via red.v2.
#define SSTRIDE 36

__global__ void __launch_bounds__(256) sgemm_tc(
    const float* __restrict__ A, const float* __restrict__ Wt,
    const float* __restrict__ bias, float* __restrict__ C, int M,
    const int* __restrict__ sidx)
{
    __shared__ float sA[128 * SSTRIDE];
    __shared__ float sB[128 * SSTRIDE];

    const int tid  = threadIdx.x;
    const int lane = tid & 31;
    const int wid  = tid >> 5;
    const int wm   = wid & 1;        // 0..1 -> 64-row slab
    const int wn   = wid >> 1;       // 0..3 -> 32-col slab
    const int row0 = blockIdx.x * 128;
    const int col0 = blockIdx.y * 128;
    const int lq   = lane >> 2;      // lane/4: 0..7
    const int lr   = lane & 3;       // lane%4: 0..3

    float acc[4][4][4];
#pragma unroll
    for (int i = 0; i < 4; i++)
#pragma unroll
        for (int j = 0; j < 4; j++)
#pragma unroll
            for (int r = 0; r < 4; r++) acc[i][j][r] = 0.f;

    for (int k0 = 0; k0 < 256; k0 += 32) {
        // ---- load A chunk: 128 rows x 32 k (4 float4 per thread) ----
#pragma unroll
        for (int ii = 0; ii < 4; ii++) {
            int i = tid + ii * 256;          // 0..1023
            int r = i >> 3, q = i & 7;       // row 0..127, float4 idx 0..7
            int grow = row0 + r;
            float4 v = make_float4(0.f, 0.f, 0.f, 0.f);
            if (grow < M) v = *reinterpret_cast<const float4*>(A + (size_t)grow * 256 + k0 + (q << 2));
            uint4 t;
            t.x = f2tf32(v.x); t.y = f2tf32(v.y); t.z = f2tf32(v.z); t.w = f2tf32(v.w);
            *reinterpret_cast<uint4*>(&sA[r * SSTRIDE + (q << 2)]) = t;
        }
        // ---- load B chunk: 128 n-rows x 32 k from Wt (K-major) ----
#pragma unroll
        for (int ii = 0; ii < 4; ii++) {
            int i = tid + ii * 256;
            int n = i >> 3, q = i & 7;
            float4 v = *reinterpret_cast<const float4*>(Wt + (size_t)(col0 + n) * 256 + k0 + (q << 2));
            uint4 t;
            t.x = f2tf32(v.x); t.y = f2tf32(v.y); t.z = f2tf32(v.z); t.w = f2tf32(v.w);
            *reinterpret_cast<uint4*>(&sB[n * SSTRIDE + (q << 2)]) = t;
        }
        __syncthreads();

        // ---- compute: 4 k-steps of 8 ----
#pragma unroll
        for (int ks = 0; ks < 4; ks++) {
            const int kk = ks * 8;
            uint32_t bf[4][2];
#pragma unroll
            for (int nt = 0; nt < 4; nt++) {
                int n = wn * 32 + nt * 8 + lq;
                bf[nt][0] = __float_as_uint(sB[n * SSTRIDE + kk + lr]);
                bf[nt][1] = __float_as_uint(sB[n * SSTRIDE + kk + 4 + lr]);
            }
#pragma unroll
            for (int mt = 0; mt < 4; mt++) {
                int m = wm * 64 + mt * 16 + lq;
                uint32_t a0 = __float_as_uint(sA[m * SSTRIDE + kk + lr]);
                uint32_t a1 = __float_as_uint(sA[(m + 8) * SSTRIDE + kk + lr]);
                uint32_t a2 = __float_as_uint(sA[m * SSTRIDE + kk + 4 + lr]);
                uint32_t a3 = __float_as_uint(sA[(m + 8) * SSTRIDE + kk + 4 + lr]);
#pragma unroll
                for (int nt = 0; nt < 4; nt++) {
                    asm volatile(
                        "mma.sync.aligned.m16n8k8.row.col.f32.tf32.tf32.f32 "
                        "{%0,%1,%2,%3}, {%4,%5,%6,%7}, {%8,%9}, {%0,%1,%2,%3};"
                        : "+f"(acc[mt][nt][0]), "+f"(acc[mt][nt][1]),
                          "+f"(acc[mt][nt][2]), "+f"(acc[mt][nt][3])
                        : "r"(a0), "r"(a1), "r"(a2), "r"(a3),
                          "r"(bf[nt][0]), "r"(bf[nt][1]));
                }
            }
        }
        __syncthreads();
    }

    // ---- epilogue ----
#pragma unroll
    for (int nt = 0; nt < 4; nt++) {
        int col = col0 + wn * 32 + nt * 8 + (lr << 1);
        float2 bv = *reinterpret_cast<const float2*>(bias + col);
#pragma unroll
        for (int mt = 0; mt < 4; mt++) {
            int rowa = row0 + wm * 64 + mt * 16 + lq;
            int rowb = rowa + 8;
            if (sidx) {
                if (rowa < M) {
                    int dr = sidx[rowa];
                    red_add_v2(C + (size_t)dr * 256 + col,
                               acc[mt][nt][0] + bv.x, acc[mt][nt][1] + bv.y);
                }
                if (rowb < M) {
                    int dr = sidx[rowb];
                    red_add_v2(C + (size_t)dr * 256 + col,
                               acc[mt][nt][2] + bv.x, acc[mt][nt][3] + bv.y);
                }
            } else {
                if (rowa < M) {
                    float2 o = make_float2(acc[mt][nt][0] + bv.x, acc[mt][nt][1] + bv.y);
                    *reinterpret_cast<float2*>(C + (size_t)rowa * 256 + col) = o;
                }
                if (rowb < M) {
                    float2 o = make_float2(acc[mt][nt][2] + bv.x, acc[mt][nt][3] + bv.y);
                    *reinterpret_cast<float2*>(C + (size_t)rowb * 256 + col) = o;
                }
            }
        }
    }
}

// ---------------- weight transpose ------------------------------------------
__global__ void transpose_W(const float* __restrict__ W) {
    int idx = blockIdx.x * 256 + threadIdx.x;
    if (idx < 9 * 65536) {
        int w = idx >> 16;
        int rc = idx & 65535;
        int r = rc >> 8, c = rc & 255;
        g_Wt[(w << 16) + (c << 8) + r] = W[idx];
    }
}

// ---------------- zero kernels ----------------------------------------------
__global__ void kzero_stage2() {
    size_t i = (size_t)blockIdx.x * blockDim.x + threadIdx.x;
    size_t n = (size_t)NA * 256;
    for (; i < n; i += (size_t)gridDim.x * blockDim.x) { g_num[i] = 0.f; g_den[i] = 0.f; }
}
__global__ void kzero_stage3() {
    size_t i = (size_t)blockIdx.x * blockDim.x + threadIdx.x;
    size_t n = (size_t)NA * 256;
    for (; i < n; i += (size_t)gridDim.x * blockDim.x) {
        g_HeA[i] = 0.f;
        if (i < NA) g_deg[i] = 0.f;
    }
}
__global__ void kzero_stats() {
    int i = threadIdx.x;
    g_sum[i] = 0.0; g_sumsq[i] = 0.0;
}

// ---------------- stage 1: edge assemble + fused BN stats -------------------
__global__ void edge_assemble(float* __restrict__ epre, const int* __restrict__ src,
                              const int* __restrict__ dst, const int* __restrict__ gid)
{
    int t = blockIdx.x * blockDim.x + threadIdx.x;   // 65536 threads
    int q = t & 63;
    int stride = (gridDim.x * blockDim.x) >> 6;
    float s0 = 0.f, s1 = 0.f, s2 = 0.f, s3 = 0.f;
    float p0 = 0.f, p1 = 0.f, p2 = 0.f, p3 = 0.f;
    for (int e = t >> 6; e < NE; e += stride) {
        int s = src[e], d = dst[e];
        int g = gid[s];
        size_t off = (size_t)e * 256 + (q << 2);
        float4 v  = *reinterpret_cast<const float4*>(epre + off);
        float4 as = *reinterpret_cast<const float4*>(g_Ah + (size_t)s * 256 + (q << 2));
        float4 ad = *reinterpret_cast<const float4*>(g_Ah + (size_t)d * 256 + (q << 2));
        float4 cu = *reinterpret_cast<const float4*>(g_Cu + (size_t)g * 256 + (q << 2));
        v.x += as.x + ad.x + cu.x;
        v.y += as.y + ad.y + cu.y;
        v.z += as.z + ad.z + cu.z;
        v.w += as.w + ad.w + cu.w;
        *reinterpret_cast<float4*>(epre + off) = v;
        s0 += v.x; p0 += v.x * v.x;
        s1 += v.y; p1 += v.y * v.y;
        s2 += v.z; p2 += v.z * v.z;
        s3 += v.w; p3 += v.w * v.w;
    }
    int c = q << 2;
    atomicAdd(&g_sum[c + 0], (double)s0); atomicAdd(&g_sumsq[c + 0], (double)p0);
    atomicAdd(&g_sum[c + 1], (double)s1); atomicAdd(&g_sumsq[c + 1], (double)p1);
    atomicAdd(&g_sum[c + 2], (double)s2); atomicAdd(&g_sumsq[c + 2], (double)p2);
    atomicAdd(&g_sum[c + 3], (double)s3); atomicAdd(&g_sumsq[c + 3], (double)p3);
}

// ---------------- BatchNorm -------------------------------------------------
__global__ void bn_stats(const float* __restrict__ X, int M)
{
    int c = threadIdx.x;
    int r0 = blockIdx.x * 256;
    int r1 = min(r0 + 256, M);
    float s = 0.f, s2 = 0.f;
    for (int r = r0; r < r1; r++) {
        float v = X[(size_t)r * 256 + c];
        s += v; s2 += v * v;
    }
    atomicAdd(&g_sum[c], (double)s);
    atomicAdd(&g_sumsq[c], (double)s2);
}

__global__ void bn_apply_relu(float* __restrict__ X, int M,
                              const float* __restrict__ gam, const float* __restrict__ bet)
{
    int c = threadIdx.x;
    double mean = g_sum[c] / M;
    double var = g_sumsq[c] / M - mean * mean;
    float scale = gam[c] * rsqrtf((float)(var + 1e-5));
    float mu = (float)mean;
    float bb = bet[c];
    for (int r = blockIdx.x; r < M; r += gridDim.x) {
        float v = (X[(size_t)r * 256 + c] - mu) * scale + bb;
        X[(size_t)r * 256 + c] = v > 0.f ? v : 0.f;
    }
}

// ---------------- stage 2: gated aggregation (vector red) -------------------
__global__ void edge_scatter(const float* __restrict__ e2, const int* __restrict__ src,
                             const int* __restrict__ dst)
{
    long long i = (long long)blockIdx.x * blockDim.x + threadIdx.x;   // NE*64 threads
    if (i >= (long long)NE * 64) return;
    int e = (int)(i >> 6), q = (int)(i & 63);
    int s = src[e], d = dst[e];
    float4 x  = *reinterpret_cast<const float4*>(e2 + (size_t)e * 256 + (q << 2));
    float4 eh = *reinterpret_cast<const float4*>(g_Eh + (size_t)s * 256 + (q << 2));
    float g0 = 1.f / (1.f + __expf(-x.x));
    float g1 = 1.f / (1.f + __expf(-x.y));
    float g2 = 1.f / (1.f + __expf(-x.z));
    float g3 = 1.f / (1.f + __expf(-x.w));
    red_add_v4(&g_num[(size_t)d * 256 + (q << 2)], g0 * eh.x, g1 * eh.y, g2 * eh.z, g3 * eh.w);
    red_add_v4(&g_den[(size_t)d * 256 + (q << 2)], g0, g1, g2, g3);
}

__global__ void h2_assemble(float* __restrict__ h2, const int* __restrict__ gid)
{
    int t = blockIdx.x * blockDim.x + threadIdx.x;
    int q = t & 63;
    int stride = (gridDim.x * blockDim.x) >> 6;
    float s0 = 0.f, s1 = 0.f, s2 = 0.f, s3 = 0.f;
    float p0 = 0.f, p1 = 0.f, p2 = 0.f, p3 = 0.f;
    for (int a = t >> 6; a < NA; a += stride) {
        int g = gid[a];
        size_t off = (size_t)a * 256 + (q << 2);
        float4 v  = *reinterpret_cast<const float4*>(h2 + off);
        float4 nu = *reinterpret_cast<const float4*>(g_num + off);
        float4 de = *reinterpret_cast<const float4*>(g_den + off);
        float4 fu = *reinterpret_cast<const float4*>(g_Fu + (size_t)g * 256 + (q << 2));
        v.x += nu.x / (de.x + 1e-6f) + fu.x;
        v.y += nu.y / (de.y + 1e-6f) + fu.y;
        v.z += nu.z / (de.z + 1e-6f) + fu.z;
        v.w += nu.w / (de.w + 1e-6f) + fu.w;
        *reinterpret_cast<float4*>(h2 + off) = v;
        s0 += v.x; p0 += v.x * v.x;
        s1 += v.y; p1 += v.y * v.y;
        s2 += v.z; p2 += v.z * v.z;
        s3 += v.w; p3 += v.w * v.w;
    }
    int c = q << 2;
    atomicAdd(&g_sum[c + 0], (double)s0); atomicAdd(&g_sumsq[c + 0], (double)p0);
    atomicAdd(&g_sum[c + 1], (double)s1); atomicAdd(&g_sumsq[c + 1], (double)p1);
    atomicAdd(&g_sum[c + 2], (double)s2); atomicAdd(&g_sumsq[c + 2], (double)p2);
    atomicAdd(&g_sum[c + 3], (double)s3); atomicAdd(&g_sumsq[c + 3], (double)p3);
}

// ---------------- stage 3 ----------------------------------------------------
__global__ void deg_count(const int* __restrict__ dst)
{
    int e = blockIdx.x * blockDim.x + threadIdx.x;
    if (e < NE) atomicAdd(&g_deg[dst[e]], 1.f);
}

__global__ void graph_reduce(float* __restrict__ u2)
{
    int g = blockIdx.x;
    int c = threadIdx.x;
    int a0 = g * APG;
    float gh = 0.f, he = 0.f;
    for (int a = a0; a < a0 + APG; a++) {
        gh += g_Gh[(size_t)a * 256 + c];
        he += g_HeA[(size_t)a * 256 + c];
    }
    __shared__ float sdeg;
    if (c == 0) {
        float dsum = 0.f;
        for (int a = a0; a < a0 + APG; a++) dsum += g_deg[a];
        sdeg = dsum;
    }
    __syncthreads();
    u2[(size_t)g * 256 + c] = gh * (1.f / APG) + he / sdeg + g_Iu[(size_t)g * 256 + c];
}

// ---------------- launch ------------------------------------------------------
extern "C" void kernel_launch(void* const* d_in, const int* in_sizes, int n_in,
                              void* d_out, int out_size)
{
    const float* h     = (const float*)d_in[0];
    const float* e     = (const float*)d_in[1];
    const float* u     = (const float*)d_in[2];
    const float* W     = (const float*)d_in[3];
    const float* b     = (const float*)d_in[4];
    const float* gamma = (const float*)d_in[5];
    const float* beta  = (const float*)d_in[6];
    const int*   src   = (const int*)d_in[7];
    const int*   dst   = (const int*)d_in[8];
    const int*   gid   = (const int*)d_in[9];

    float* out_h2 = (float*)d_out;
    float* out_e2 = out_h2 + (size_t)NA * 256;
    float* out_u2 = out_e2 + (size_t)NE * 256;

    float *pAh, *pEh, *pCu, *pFu, *pIu, *pGh, *pHeA, *pWt;
    cudaGetSymbolAddress((void**)&pAh, g_Ah);
    cudaGetSymbolAddress((void**)&pEh, g_Eh);
    cudaGetSymbolAddress((void**)&pCu, g_Cu);
    cudaGetSymbolAddress((void**)&pFu, g_Fu);
    cudaGetSymbolAddress((void**)&pIu, g_Iu);
    cudaGetSymbolAddress((void**)&pGh, g_Gh);
    cudaGetSymbolAddress((void**)&pHeA, g_HeA);
    cudaGetSymbolAddress((void**)&pWt, g_Wt);

    dim3 gA((NA + 127) / 128, 2);
    dim3 gE((NE + 127) / 128, 2);
    dim3 gU((NG + 127) / 128, 2);

    transpose_W<<<(9 * 65536 + 255) / 256, 256>>>(W);
    kzero_stats<<<1, 256>>>();
    kzero_stage2<<<2048, 256>>>();

    // ---- stage 1: edge update ----
    sgemm_tc<<<gA, 256>>>(h, pWt + 0 * 65536, b + 0 * 256, pAh, NA, nullptr);     // Ah
    sgemm_tc<<<gE, 256>>>(e, pWt + 1 * 65536, b + 1 * 256, out_e2, NE, nullptr);  // Be
    sgemm_tc<<<gU, 256>>>(u, pWt + 2 * 65536, b + 2 * 256, pCu, NG, nullptr);     // Cu
    edge_assemble<<<256, 256>>>(out_e2, src, dst, gid);                           // + BN stats
    bn_apply_relu<<<4096, 256>>>(out_e2, NE, gamma + 256, beta + 256);

    // ---- stage 2: atom update ----
    kzero_stats<<<1, 256>>>();
    sgemm_tc<<<gA, 256>>>(h, pWt + 4 * 65536, b + 4 * 256, pEh, NA, nullptr);     // Eh
    sgemm_tc<<<gA, 256>>>(h, pWt + 3 * 65536, b + 3 * 256, out_h2, NA, nullptr);  // Dh
    sgemm_tc<<<gU, 256>>>(u, pWt + 5 * 65536, b + 5 * 256, pFu, NG, nullptr);     // Fu
    edge_scatter<<<(int)(((long long)NE * 64 + 255) / 256), 256>>>(out_e2, src, dst);
    h2_assemble<<<256, 256>>>(out_h2, gid);                                       // + BN stats
    bn_apply_relu<<<4096, 256>>>(out_h2, NA, gamma, beta);

    // ---- stage 3: global update ----
    kzero_stage3<<<2048, 256>>>();
    kzero_stats<<<1, 256>>>();
    sgemm_tc<<<gA, 256>>>(out_h2, pWt + 6 * 65536, b + 6 * 256, pGh, NA, nullptr);   // Gh
    sgemm_tc<<<gE, 256>>>(out_e2, pWt + 7 * 65536, b + 7 * 256, pHeA, NE, dst);      // He scatter
    sgemm_tc<<<gU, 256>>>(u, pWt + 8 * 65536, b + 8 * 256, pIu, NG, nullptr);        // Iu
    deg_count<<<(NE + 255) / 256, 256>>>(dst);
    graph_reduce<<<NG, 256>>>(out_u2);
    bn_stats<<<(NG + 255) / 256, 256>>>(out_u2, NG);
    bn_apply_relu<<<2000, 256>>>(out_u2, NG, gamma + 512, beta + 512);
}

// round 4
// speedup vs baseline: 2.3318x; 1.1906x over previous
#include <cuda_runtime.h>
#include <cstdint>
#include <math.h>

#define NA 80000
#define NE 250000
#define NG 2000
#define APG 40
#define SST 44   // smem row stride in floats: 176B, 16B-aligned, conflict-free

// ---------------- device scratch (no allocation allowed) ---------------------
__device__ float g_Ah[NA * 256];
__device__ float g_Eh[NA * 256];
__device__ float g_Cu[NG * 256];
__device__ float g_Fu[NG * 256];
__device__ float g_Iu[NG * 256];
__device__ float g_num[NA * 256];
__device__ float g_den[NA * 256];
__device__ float g_Gh[NA * 256];
__device__ float g_HeA[NA * 256];
__device__ float g_deg[NA];
__device__ float g_Wt[9 * 256 * 256];    // group-ordered, transposed, tf32-rounded
__device__ float g_bias[9 * 256];        // group-ordered biases
__device__ float g_hT[NA * 256];         // tf32-rounded h
__device__ float g_eT[NE * 256];         // tf32-rounded e
__device__ float g_uT[NG * 256];         // tf32-rounded u
__device__ float g_h2T[NA * 256];        // tf32-rounded h2 (post BN)
__device__ float g_e2T[NE * 256];        // tf32-rounded e2 (post BN)
__device__ double g_sumN[3 * 256];
__device__ double g_sumsqN[3 * 256];
__device__ float g_bnA[256];
__device__ float g_bnB[256];

// slot order: A0,D3,E4 | B1 | C2,F5,I8 | G6 | H7  -> orig idx -> slot
__constant__ int c_slot[9] = {0, 3, 4, 1, 2, 5, 7, 8, 6};

// ---------------- helpers -----------------------------------------------------
__device__ __forceinline__ uint32_t smem_u32(const void* p) {
    uint32_t a;
    asm("{ .reg .u64 t; cvta.to.shared.u64 t, %1; cvt.u32.u64 %0, t; }" : "=r"(a) : "l"(p));
    return a;
}
__device__ __forceinline__ uint32_t f2tf32(float v) {
    uint32_t u;
    asm("cvt.rna.tf32.f32 %0, %1;" : "=r"(u) : "f"(v));
    return u;
}
__device__ __forceinline__ void red_add_v4(float* addr, float a, float b, float c, float d) {
    asm volatile("red.global.add.v4.f32 [%0], {%1, %2, %3, %4};"
        :: "l"(addr), "f"(a), "f"(b), "f"(c), "f"(d) : "memory");
}
__device__ __forceinline__ void red_add_v2(float* addr, float a, float b) {
    asm volatile("red.global.add.v2.f32 [%0], {%1, %2};"
        :: "l"(addr), "f"(a), "f"(b) : "memory");
}

// ---------------- tf32 mma.sync GEMM with cp.async double buffering ----------
// CTA tile 128x128. grid.y = 2*nW: w = y>>1 selects weight/output, half = y&1.
// A must be pre-rounded to tf32. Wt group-ordered K-major [w][n][k].
// buffers: buf stride = 2*128*SST floats; sA then sB.
__global__ void __launch_bounds__(256, 2) sgemm_tc(
    const float* __restrict__ A, const float* __restrict__ WtG,
    const float* __restrict__ biasG, float* __restrict__ C0,
    float* __restrict__ C1, float* __restrict__ C2, int M,
    const int* __restrict__ sidx)
{
    extern __shared__ float sm[];
    const int tid  = threadIdx.x;
    const int lane = tid & 31;
    const int wid  = tid >> 5;
    const int wm   = wid & 1;
    const int wn   = wid >> 1;
    const int row0 = blockIdx.x * 128;
    const int w    = blockIdx.y >> 1;
    const int half = blockIdx.y & 1;
    const int col0 = half * 128;
    const int lq   = lane >> 2;
    const int lr   = lane & 3;

    const float* Wt   = WtG + w * 65536;
    const float* bias = biasG + w * 256;
    float* C = (w == 0) ? C0 : ((w == 1) ? C1 : C2);

    const uint32_t smbase = smem_u32(sm);
    const uint32_t BUFB = 128 * SST * 4;          // bytes per array
    const uint32_t BUFS = 2 * BUFB;               // bytes per buffer (A+B)

    // issue cp.async for chunk c into buffer c&1
    auto load_chunk = [&](int c) {
        const int buf = c & 1;
        const int k0  = c * 32;
        const uint32_t abase = smbase + buf * BUFS;
        const uint32_t bbase = abase + BUFB;
#pragma unroll
        for (int ii = 0; ii < 4; ii++) {
            int i = tid + ii * 256;
            int r = i >> 3, q = i & 7;
            int grow = row0 + r;
            const float* src = A + (size_t)grow * 256 + k0 + (q << 2);
            uint32_t dst = abase + (uint32_t)(r * SST + (q << 2)) * 4;
            int sz = (grow < M) ? 16 : 0;
            asm volatile("cp.async.ca.shared.global [%0], [%1], 16, %2;"
                :: "r"(dst), "l"(src), "r"(sz) : "memory");
        }
#pragma unroll
        for (int ii = 0; ii < 4; ii++) {
            int i = tid + ii * 256;
            int n = i >> 3, q = i & 7;
            const float* src = Wt + (size_t)(col0 + n) * 256 + k0 + (q << 2);
            uint32_t dst = bbase + (uint32_t)(n * SST + (q << 2)) * 4;
            asm volatile("cp.async.ca.shared.global [%0], [%1], 16;"
                :: "r"(dst), "l"(src) : "memory");
        }
        asm volatile("cp.async.commit_group;" ::: "memory");
    };

    float acc[4][4][4];
#pragma unroll
    for (int i = 0; i < 4; i++)
#pragma unroll
        for (int j = 0; j < 4; j++)
#pragma unroll
            for (int r = 0; r < 4; r++) acc[i][j][r] = 0.f;

    load_chunk(0);
    load_chunk(1);

    for (int c = 0; c < 8; c++) {
        if (c < 7) asm volatile("cp.async.wait_group 1;" ::: "memory");
        else       asm volatile("cp.async.wait_group 0;" ::: "memory");
        __syncthreads();
        const float* sA = sm + (c & 1) * (2 * 128 * SST);
        const float* sB = sA + 128 * SST;

#pragma unroll
        for (int ks = 0; ks < 4; ks++) {
            const int kk = ks * 8;
            uint32_t bf[4][2];
#pragma unroll
            for (int nt = 0; nt < 4; nt++) {
                int n = wn * 32 + nt * 8 + lq;
                bf[nt][0] = __float_as_uint(sB[n * SST + kk + lr]);
                bf[nt][1] = __float_as_uint(sB[n * SST + kk + 4 + lr]);
            }
#pragma unroll
            for (int mt = 0; mt < 4; mt++) {
                int m = wm * 64 + mt * 16 + lq;
                uint32_t a0 = __float_as_uint(sA[m * SST + kk + lr]);
                uint32_t a1 = __float_as_uint(sA[(m + 8) * SST + kk + lr]);
                uint32_t a2 = __float_as_uint(sA[m * SST + kk + 4 + lr]);
                uint32_t a3 = __float_as_uint(sA[(m + 8) * SST + kk + 4 + lr]);
#pragma unroll
                for (int nt = 0; nt < 4; nt++) {
                    asm volatile(
                        "mma.sync.aligned.m16n8k8.row.col.f32.tf32.tf32.f32 "
                        "{%0,%1,%2,%3}, {%4,%5,%6,%7}, {%8,%9}, {%0,%1,%2,%3};"
                        : "+f"(acc[mt][nt][0]), "+f"(acc[mt][nt][1]),
                          "+f"(acc[mt][nt][2]), "+f"(acc[mt][nt][3])
                        : "r"(a0), "r"(a1), "r"(a2), "r"(a3),
                          "r"(bf[nt][0]), "r"(bf[nt][1]));
                }
            }
        }
        __syncthreads();
        if (c + 2 < 8) load_chunk(c + 2);
    }

    // ---- epilogue ----
#pragma unroll
    for (int nt = 0; nt < 4; nt++) {
        int col = col0 + wn * 32 + nt * 8 + (lr << 1);
        float2 bv = *reinterpret_cast<const float2*>(bias + col);
#pragma unroll
        for (int mt = 0; mt < 4; mt++) {
            int rowa = row0 + wm * 64 + mt * 16 + lq;
            int rowb = rowa + 8;
            if (sidx) {
                if (rowa < M) {
                    int dr = sidx[rowa];
                    red_add_v2(C + (size_t)dr * 256 + col,
                               acc[mt][nt][0] + bv.x, acc[mt][nt][1] + bv.y);
                }
                if (rowb < M) {
                    int dr = sidx[rowb];
                    red_add_v2(C + (size_t)dr * 256 + col,
                               acc[mt][nt][2] + bv.x, acc[mt][nt][3] + bv.y);
                }
            } else {
                if (rowa < M) {
                    float2 o = make_float2(acc[mt][nt][0] + bv.x, acc[mt][nt][1] + bv.y);
                    *reinterpret_cast<float2*>(C + (size_t)rowa * 256 + col) = o;
                }
                if (rowb < M) {
                    float2 o = make_float2(acc[mt][nt][2] + bv.x, acc[mt][nt][3] + bv.y);
                    *reinterpret_cast<float2*>(C + (size_t)rowb * 256 + col) = o;
                }
            }
        }
    }
}

// ---------------- weight transpose + round + bias reorder -------------------
__global__ void transpose_W(const float* __restrict__ W, const float* __restrict__ b) {
    int idx = blockIdx.x * 256 + threadIdx.x;
    if (idx < 9 * 65536) {
        int w = idx >> 16;
        int rc = idx & 65535;
        int r = rc >> 8, c = rc & 255;
        g_Wt[(c_slot[w] << 16) + (c << 8) + r] = __uint_as_float(f2tf32(W[idx]));
    }
    if (idx < 9 * 256) {
        int w = idx >> 8;
        g_bias[(c_slot[w] << 8) + (idx & 255)] = b[idx];
    }
}

// ---------------- tf32 round copy -------------------------------------------
__global__ void round_copy(float* __restrict__ dst, const float* __restrict__ src, int n4) {
    int i = blockIdx.x * blockDim.x + threadIdx.x;
    for (; i < n4; i += gridDim.x * blockDim.x) {
        float4 v = reinterpret_cast<const float4*>(src)[i];
        uint4 t;
        t.x = f2tf32(v.x); t.y = f2tf32(v.y); t.z = f2tf32(v.z); t.w = f2tf32(v.w);
        reinterpret_cast<uint4*>(dst)[i] = t;
    }
}

// ---------------- one-shot zeroing -------------------------------------------
__global__ void zero_all() {
    size_t i = (size_t)blockIdx.x * blockDim.x + threadIdx.x;
    size_t n = (size_t)NA * 256;
    size_t stride = (size_t)gridDim.x * blockDim.x;
    for (size_t j = i; j < n; j += stride) {
        g_num[j] = 0.f; g_den[j] = 0.f; g_HeA[j] = 0.f;
    }
    if (i < NA) g_deg[i] = 0.f;
    if (i < 768) { g_sumN[i] = 0.0; g_sumsqN[i] = 0.0; }
}

// ---------------- stage 1: edge assemble + fused BN stats (set 1) -----------
__global__ void edge_assemble(float* __restrict__ epre, const int* __restrict__ src,
                              const int* __restrict__ dst, const int* __restrict__ gid)
{
    int t = blockIdx.x * blockDim.x + threadIdx.x;
    int q = t & 63;
    int stride = (gridDim.x * blockDim.x) >> 6;
    float s0 = 0.f, s1 = 0.f, s2 = 0.f, s3 = 0.f;
    float p0 = 0.f, p1 = 0.f, p2 = 0.f, p3 = 0.f;
    for (int e = t >> 6; e < NE; e += stride) {
        int s = src[e], d = dst[e];
        int g = gid[s];
        size_t off = (size_t)e * 256 + (q << 2);
        float4 v  = *reinterpret_cast<const float4*>(epre + off);
        float4 as = *reinterpret_cast<const float4*>(g_Ah + (size_t)s * 256 + (q << 2));
        float4 ad = *reinterpret_cast<const float4*>(g_Ah + (size_t)d * 256 + (q << 2));
        float4 cu = *reinterpret_cast<const float4*>(g_Cu + (size_t)g * 256 + (q << 2));
        v.x += as.x + ad.x + cu.x;
        v.y += as.y + ad.y + cu.y;
        v.z += as.z + ad.z + cu.z;
        v.w += as.w + ad.w + cu.w;
        *reinterpret_cast<float4*>(epre + off) = v;
        s0 += v.x; p0 += v.x * v.x;
        s1 += v.y; p1 += v.y * v.y;
        s2 += v.z; p2 += v.z * v.z;
        s3 += v.w; p3 += v.w * v.w;
    }
    int c = 256 + (q << 2);
    atomicAdd(&g_sumN[c + 0], (double)s0); atomicAdd(&g_sumsqN[c + 0], (double)p0);
    atomicAdd(&g_sumN[c + 1], (double)s1); atomicAdd(&g_sumsqN[c + 1], (double)p1);
    atomicAdd(&g_sumN[c + 2], (double)s2); atomicAdd(&g_sumsqN[c + 2], (double)p2);
    atomicAdd(&g_sumN[c + 3], (double)s3); atomicAdd(&g_sumsqN[c + 3], (double)p3);
}

// ---------------- BN finalize: stats set -> float scale/bias ----------------
__global__ void bn_finalize(int set, int M, const float* __restrict__ gam,
                            const float* __restrict__ bet)
{
    int c = threadIdx.x;
    double mean = g_sumN[set * 256 + c] / M;
    double var  = g_sumsqN[set * 256 + c] / M - mean * mean;
    float scale = gam[c] * rsqrtf((float)(var + 1e-5));
    g_bnA[c] = scale;
    g_bnB[c] = bet[c] - (float)mean * scale;
}

// ---------------- fused BN-apply(e2) + sigmoid scatter + deg ----------------
__global__ void bn_scatter_e2(float* __restrict__ e2, const int* __restrict__ src,
                              const int* __restrict__ dst)
{
    long long i = (long long)blockIdx.x * blockDim.x + threadIdx.x;
    if (i >= (long long)NE * 64) return;
    int e = (int)(i >> 6), q = (int)(i & 63);
    int c = q << 2;
    float4 sc = *reinterpret_cast<const float4*>(g_bnA + c);
    float4 bb = *reinterpret_cast<const float4*>(g_bnB + c);
    size_t off = (size_t)e * 256 + c;
    float4 v = *reinterpret_cast<const float4*>(e2 + off);
    v.x = fmaxf(v.x * sc.x + bb.x, 0.f);
    v.y = fmaxf(v.y * sc.y + bb.y, 0.f);
    v.z = fmaxf(v.z * sc.z + bb.z, 0.f);
    v.w = fmaxf(v.w * sc.w + bb.w, 0.f);
    *reinterpret_cast<float4*>(e2 + off) = v;
    uint4 t;
    t.x = f2tf32(v.x); t.y = f2tf32(v.y); t.z = f2tf32(v.z); t.w = f2tf32(v.w);
    *reinterpret_cast<uint4*>(g_e2T + off) = t;
    int s = src[e], d = dst[e];
    float4 eh = *reinterpret_cast<const float4*>(g_Eh + (size_t)s * 256 + c);
    float g0 = 1.f / (1.f + __expf(-v.x));
    float g1 = 1.f / (1.f + __expf(-v.y));
    float g2 = 1.f / (1.f + __expf(-v.z));
    float g3 = 1.f / (1.f + __expf(-v.w));
    red_add_v4(&g_num[(size_t)d * 256 + c], g0 * eh.x, g1 * eh.y, g2 * eh.z, g3 * eh.w);
    red_add_v4(&g_den[(size_t)d * 256 + c], g0, g1, g2, g3);
    if (q == 0) atomicAdd(&g_deg[d], 1.f);
}

// ---------------- stage 2: h2 assemble + fused BN stats (set 0) -------------
__global__ void h2_assemble(float* __restrict__ h2, const int* __restrict__ gid)
{
    int t = blockIdx.x * blockDim.x + threadIdx.x;
    int q = t & 63;
    int stride = (gridDim.x * blockDim.x) >> 6;
    float s0 = 0.f, s1 = 0.f, s2 = 0.f, s3 = 0.f;
    float p0 = 0.f, p1 = 0.f, p2 = 0.f, p3 = 0.f;
    for (int a = t >> 6; a < NA; a += stride) {
        int g = gid[a];
        size_t off = (size_t)a * 256 + (q << 2);
        float4 v  = *reinterpret_cast<const float4*>(h2 + off);
        float4 nu = *reinterpret_cast<const float4*>(g_num + off);
        float4 de = *reinterpret_cast<const float4*>(g_den + off);
        float4 fu = *reinterpret_cast<const float4*>(g_Fu + (size_t)g * 256 + (q << 2));
        v.x += nu.x / (de.x + 1e-6f) + fu.x;
        v.y += nu.y / (de.y + 1e-6f) + fu.y;
        v.z += nu.z / (de.z + 1e-6f) + fu.z;
        v.w += nu.w / (de.w + 1e-6f) + fu.w;
        *reinterpret_cast<float4*>(h2 + off) = v;
        s0 += v.x; p0 += v.x * v.x;
        s1 += v.y; p1 += v.y * v.y;
        s2 += v.z; p2 += v.z * v.z;
        s3 += v.w; p3 += v.w * v.w;
    }
    int c = q << 2;
    atomicAdd(&g_sumN[c + 0], (double)s0); atomicAdd(&g_sumsqN[c + 0], (double)p0);
    atomicAdd(&g_sumN[c + 1], (double)s1); atomicAdd(&g_sumsqN[c + 1], (double)p1);
    atomicAdd(&g_sumN[c + 2], (double)s2); atomicAdd(&g_sumsqN[c + 2], (double)p2);
    atomicAdd(&g_sumN[c + 3], (double)s3); atomicAdd(&g_sumsqN[c + 3], (double)p3);
}

// ---------------- BN apply h2 (writes f32 + tf32 copy) ----------------------
__global__ void bn_apply_h2(float* __restrict__ h2)
{
    long long i = (long long)blockIdx.x * blockDim.x + threadIdx.x;
    if (i >= (long long)NA * 64) return;
    int a = (int)(i >> 6), q = (int)(i & 63);
    int c = q << 2;
    float4 sc = *reinterpret_cast<const float4*>(g_bnA + c);
    float4 bb = *reinterpret_cast<const float4*>(g_bnB + c);
    size_t off = (size_t)a * 256 + c;
    float4 v = *reinterpret_cast<const float4*>(h2 + off);
    v.x = fmaxf(v.x * sc.x + bb.x, 0.f);
    v.y = fmaxf(v.y * sc.y + bb.y, 0.f);
    v.z = fmaxf(v.z * sc.z + bb.z, 0.f);
    v.w = fmaxf(v.w * sc.w + bb.w, 0.f);
    *reinterpret_cast<float4*>(h2 + off) = v;
    uint4 t;
    t.x = f2tf32(v.x); t.y = f2tf32(v.y); t.z = f2tf32(v.z); t.w = f2tf32(v.w);
    *reinterpret_cast<uint4*>(g_h2T + off) = t;
}

// ---------------- BN apply u2 (no copy) --------------------------------------
__global__ void bn_apply_u2(float* __restrict__ u2)
{
    int i = blockIdx.x * blockDim.x + threadIdx.x;
    if (i >= NG * 64) return;
    int a = i >> 6, q = i & 63;
    int c = q << 2;
    float4 sc = *reinterpret_cast<const float4*>(g_bnA + c);
    float4 bb = *reinterpret_cast<const float4*>(g_bnB + c);
    size_t off = (size_t)a * 256 + c;
    float4 v = *reinterpret_cast<const float4*>(u2 + off);
    v.x = fmaxf(v.x * sc.x + bb.x, 0.f);
    v.y = fmaxf(v.y * sc.y + bb.y, 0.f);
    v.z = fmaxf(v.z * sc.z + bb.z, 0.f);
    v.w = fmaxf(v.w * sc.w + bb.w, 0.f);
    *reinterpret_cast<float4*>(u2 + off) = v;
}

// ---------------- stage 3 -----------------------------------------------------
__global__ void bn_stats(const float* __restrict__ X, int M, int set)
{
    int c = threadIdx.x;
    int r0 = blockIdx.x * 256;
    int r1 = min(r0 + 256, M);
    float s = 0.f, s2 = 0.f;
    for (int r = r0; r < r1; r++) {
        float v = X[(size_t)r * 256 + c];
        s += v; s2 += v * v;
    }
    atomicAdd(&g_sumN[set * 256 + c], (double)s);
    atomicAdd(&g_sumsqN[set * 256 + c], (double)s2);
}

__global__ void graph_reduce(float* __restrict__ u2)
{
    int g = blockIdx.x;
    int c = threadIdx.x;
    int a0 = g * APG;
    float gh = 0.f, he = 0.f;
    for (int a = a0; a < a0 + APG; a++) {
        gh += g_Gh[(size_t)a * 256 + c];
        he += g_HeA[(size_t)a * 256 + c];
    }
    __shared__ float sdeg;
    if (c == 0) {
        float dsum = 0.f;
        for (int a = a0; a < a0 + APG; a++) dsum += g_deg[a];
        sdeg = dsum;
    }
    __syncthreads();
    u2[(size_t)g * 256 + c] = gh * (1.f / APG) + he / sdeg + g_Iu[(size_t)g * 256 + c];
}

// ---------------- launch ------------------------------------------------------
extern "C" void kernel_launch(void* const* d_in, const int* in_sizes, int n_in,
                              void* d_out, int out_size)
{
    const float* h     = (const float*)d_in[0];
    const float* e     = (const float*)d_in[1];
    const float* u     = (const float*)d_in[2];
    const float* W     = (const float*)d_in[3];
    const float* b     = (const float*)d_in[4];
    const float* gamma = (const float*)d_in[5];
    const float* beta  = (const float*)d_in[6];
    const int*   src   = (const int*)d_in[7];
    const int*   dst   = (const int*)d_in[8];
    const int*   gid   = (const int*)d_in[9];

    float* out_h2 = (float*)d_out;
    float* out_e2 = out_h2 + (size_t)NA * 256;
    float* out_u2 = out_e2 + (size_t)NE * 256;

    float *pAh, *pEh, *pCu, *pFu, *pIu, *pGh, *pHeA, *pWt, *pBias;
    float *phT, *peT, *puT, *ph2T, *pe2T;
    cudaGetSymbolAddress((void**)&pAh, g_Ah);
    cudaGetSymbolAddress((void**)&pEh, g_Eh);
    cudaGetSymbolAddress((void**)&pCu, g_Cu);
    cudaGetSymbolAddress((void**)&pFu, g_Fu);
    cudaGetSymbolAddress((void**)&pIu, g_Iu);
    cudaGetSymbolAddress((void**)&pGh, g_Gh);
    cudaGetSymbolAddress((void**)&pHeA, g_HeA);
    cudaGetSymbolAddress((void**)&pWt, g_Wt);
    cudaGetSymbolAddress((void**)&pBias, g_bias);
    cudaGetSymbolAddress((void**)&phT, g_hT);
    cudaGetSymbolAddress((void**)&peT, g_eT);
    cudaGetSymbolAddress((void**)&puT, g_uT);
    cudaGetSymbolAddress((void**)&ph2T, g_h2T);
    cudaGetSymbolAddress((void**)&pe2T, g_e2T);

    const int SMEM = 2 * 2 * 128 * SST * 4;   // 90112 B
    static int attr_done = 0;
    if (!attr_done) {
        cudaFuncSetAttribute(sgemm_tc, cudaFuncAttributeMaxDynamicSharedMemorySize, SMEM);
        attr_done = 1;
    }

    dim3 gH((NA + 127) / 128, 6);    // A,D,E on h
    dim3 gB((NE + 127) / 128, 2);    // B on e
    dim3 gUU((NG + 127) / 128, 6);   // C,F,I on u
    dim3 gG((NA + 127) / 128, 2);    // G on h2
    dim3 gHe((NE + 127) / 128, 2);   // H on e2 (scatter)

    zero_all<<<2048, 256>>>();
    transpose_W<<<(9 * 65536 + 255) / 256, 256>>>(W, b);
    round_copy<<<2048, 256>>>(phT, h, NA * 64);
    round_copy<<<4096, 256>>>(peT, e, NE * 64);
    round_copy<<<512, 256>>>(puT, u, NG * 64);

    // ---- stage 1 + inputs of stage 2 ----
    sgemm_tc<<<gH, 256, SMEM>>>(phT, pWt + 0 * 65536, pBias + 0 * 256,
                                pAh, out_h2, pEh, NA, nullptr);        // Ah, Dh, Eh
    sgemm_tc<<<gB, 256, SMEM>>>(peT, pWt + 3 * 65536, pBias + 3 * 256,
                                out_e2, nullptr, nullptr, NE, nullptr); // Be
    sgemm_tc<<<gUU, 256, SMEM>>>(puT, pWt + 4 * 65536, pBias + 4 * 256,
                                 pCu, pFu, pIu, NG, nullptr);           // Cu, Fu, Iu
    edge_assemble<<<256, 256>>>(out_e2, src, dst, gid);                 // + stats set1
    bn_finalize<<<1, 256>>>(1, NE, gamma + 256, beta + 256);
    bn_scatter_e2<<<(int)(((long long)NE * 64 + 255) / 256), 256>>>(out_e2, src, dst);

    // ---- stage 2 ----
    h2_assemble<<<256, 256>>>(out_h2, gid);                             // + stats set0
    bn_finalize<<<1, 256>>>(0, NA, gamma, beta);
    bn_apply_h2<<<(int)(((long long)NA * 64 + 255) / 256), 256>>>(out_h2);

    // ---- stage 3 ----
    sgemm_tc<<<gG, 256, SMEM>>>(ph2T, pWt + 7 * 65536, pBias + 7 * 256,
                                pGh, nullptr, nullptr, NA, nullptr);    // Gh
    sgemm_tc<<<gHe, 256, SMEM>>>(pe2T, pWt + 8 * 65536, pBias + 8 * 256,
                                 pHeA, nullptr, nullptr, NE, dst);      // He scatter
    graph_reduce<<<NG, 256>>>(out_u2);
    bn_stats<<<(NG + 255) / 256, 256>>>(out_u2, NG, 2);
    bn_finalize<<<1, 256>>>(2, NG, gamma + 512, beta + 512);
    bn_apply_u2<<<(NG * 64 + 255) / 256, 256>>>(out_u2);
}

// round 5
// speedup vs baseline: 2.5768x; 1.1051x over previous
#include <cuda_runtime.h>
#include <cstdint>
#include <math.h>

#define NA 80000
#define NE 250000
#define NG 2000
#define APG 40

// ---------------- device scratch (no allocation allowed) ---------------------
__device__ float g_Ah[NA * 256];
__device__ float g_Eh[NA * 256];
__device__ float g_Cu[NG * 256];
__device__ float g_Fu[NG * 256];
__device__ float g_num[NA * 256];     // zero-restored by h2_assemble
__device__ float g_den[NA * 256];     // zero-restored by h2_assemble
__device__ float g_esum[NA * 256];    // zero-restored by graph_collect
__device__ float g_degG[NG];          // zero-restored by graph_collect
__device__ float g_Wt[6 * 256 * 256]; // slots 0..5, K-major [slot][n][k], tf32-rounded
__device__ float g_Wcat[256 * 768];   // [n][k0..767] = W6|W7|W8 K-major, tf32-rounded
__device__ float g_bias[6 * 256];
__device__ float g_bcat[256];         // b6+b7+b8
__device__ float g_Acat[NG * 768];    // [Sh/40 | Se/deg | u]
__device__ double g_sumN[3 * 256];    // zero-restored by bn_finalize
__device__ double g_sumsqN[3 * 256];
__device__ float g_bnA[256];
__device__ float g_bnB[256];

// orig W idx -> slot:  W0->0(A) W1->3(B) W2->4(C) W3->1(D) W4->2(E) W5->5(F)
__constant__ int c_slot6[6] = {0, 3, 4, 1, 2, 5};

// ---------------- helpers -----------------------------------------------------
__device__ __forceinline__ uint32_t smem_u32(const void* p) {
    uint32_t a;
    asm("{ .reg .u64 t; cvta.to.shared.u64 t, %1; cvt.u32.u64 %0, t; }" : "=r"(a) : "l"(p));
    return a;
}
__device__ __forceinline__ uint32_t f2tf32(float v) {
    uint32_t u;
    asm("cvt.rna.tf32.f32 %0, %1;" : "=r"(u) : "f"(v));
    return u;
}
__device__ __forceinline__ void red_add_v4(float* addr, float a, float b, float c, float d) {
    asm volatile("red.global.add.v4.f32 [%0], {%1, %2, %3, %4};"
        :: "l"(addr), "f"(a), "f"(b), "f"(c), "f"(d) : "memory");
}

// ---------------- tf32 mma GEMM, 3-stage cp.async, swizzled smem -------------
// CTA tile 128x128. grid.y = 2*nSlots: w = y>>1 weight slot, half = y&1.
// A raw f32 (HW truncates to tf32), row stride K. Wt K-major [n][k] rounded.
__global__ void __launch_bounds__(256, 2) sgemm_tc(
    const float* __restrict__ A, const float* __restrict__ WtG,
    const float* __restrict__ biasG, float* __restrict__ C0,
    float* __restrict__ C1, float* __restrict__ C2, int M, int K)
{
    extern __shared__ float sm[];
    const int tid  = threadIdx.x;
    const int lane = tid & 31;
    const int wid  = tid >> 5;
    const int wm   = wid & 1;
    const int wn   = wid >> 1;
    const int row0 = blockIdx.x * 128;
    const int w    = blockIdx.y >> 1;
    const int half = blockIdx.y & 1;
    const int col0 = half * 128;
    const int lq   = lane >> 2;
    const int lr   = lane & 3;

    const float* Wt   = WtG + (size_t)w * K * 256;
    const float* bias = biasG + w * 256;
    float* C = (w == 0) ? C0 : ((w == 1) ? C1 : C2);

    const uint32_t smbase = smem_u32(sm);
    const int chunks = K >> 5;

    auto load_chunk = [&](int c) {
        const int st = c % 3;
        const int k0 = c << 5;
        const uint32_t abase = smbase + st * 32768;
        const uint32_t bbase = abase + 16384;
#pragma unroll
        for (int ii = 0; ii < 4; ii++) {
            int i = tid + (ii << 8);
            int r = i >> 3, q = i & 7;
            int grow = row0 + r;
            const float* srcp = A + (size_t)grow * K + k0 + (q << 2);
            uint32_t dstA = abase + (uint32_t)((r << 5) + ((q ^ (r & 7)) << 2)) * 4;
            int sz = (grow < M) ? 16 : 0;
            asm volatile("cp.async.ca.shared.global [%0], [%1], 16, %2;"
                :: "r"(dstA), "l"(srcp), "r"(sz) : "memory");
        }
#pragma unroll
        for (int ii = 0; ii < 4; ii++) {
            int i = tid + (ii << 8);
            int n = i >> 3, q = i & 7;
            const float* srcp = Wt + (size_t)(col0 + n) * K + k0 + (q << 2);
            uint32_t dstB = bbase + (uint32_t)((n << 5) + ((q ^ (n & 7)) << 2)) * 4;
            asm volatile("cp.async.ca.shared.global [%0], [%1], 16;"
                :: "r"(dstB), "l"(srcp) : "memory");
        }
        asm volatile("cp.async.commit_group;" ::: "memory");
    };

    float acc[4][4][4];
#pragma unroll
    for (int i = 0; i < 4; i++)
#pragma unroll
        for (int j = 0; j < 4; j++)
#pragma unroll
            for (int r = 0; r < 4; r++) acc[i][j][r] = 0.f;

    load_chunk(0);
    if (chunks > 1) load_chunk(1);

    for (int c = 0; c < chunks; c++) {
        if (c + 1 < chunks) asm volatile("cp.async.wait_group 1;" ::: "memory");
        else                asm volatile("cp.async.wait_group 0;" ::: "memory");
        __syncthreads();
        if (c + 2 < chunks) load_chunk(c + 2);
        const float* sA = sm + (c % 3) * 8192;
        const float* sB = sA + 4096;

#pragma unroll
        for (int ks = 0; ks < 4; ks++) {
            const int s0 = (((2 * ks) ^ lq) << 2) + lr;
            const int s1 = (((2 * ks + 1) ^ lq) << 2) + lr;
            uint32_t bf[4][2];
#pragma unroll
            for (int nt = 0; nt < 4; nt++) {
                int n = wn * 32 + nt * 8 + lq;
                bf[nt][0] = __float_as_uint(sB[(n << 5) + s0]);
                bf[nt][1] = __float_as_uint(sB[(n << 5) + s1]);
            }
#pragma unroll
            for (int mt = 0; mt < 4; mt++) {
                int m = wm * 64 + mt * 16 + lq;
                uint32_t a0 = __float_as_uint(sA[(m << 5) + s0]);
                uint32_t a1 = __float_as_uint(sA[((m + 8) << 5) + s0]);
                uint32_t a2 = __float_as_uint(sA[(m << 5) + s1]);
                uint32_t a3 = __float_as_uint(sA[((m + 8) << 5) + s1]);
#pragma unroll
                for (int nt = 0; nt < 4; nt++) {
                    asm volatile(
                        "mma.sync.aligned.m16n8k8.row.col.f32.tf32.tf32.f32 "
                        "{%0,%1,%2,%3}, {%4,%5,%6,%7}, {%8,%9}, {%0,%1,%2,%3};"
                        : "+f"(acc[mt][nt][0]), "+f"(acc[mt][nt][1]),
                          "+f"(acc[mt][nt][2]), "+f"(acc[mt][nt][3])
                        : "r"(a0), "r"(a1), "r"(a2), "r"(a3),
                          "r"(bf[nt][0]), "r"(bf[nt][1]));
                }
            }
        }
    }

    // ---- epilogue (C always 256 cols) ----
#pragma unroll
    for (int nt = 0; nt < 4; nt++) {
        int col = col0 + wn * 32 + nt * 8 + (lr << 1);
        float2 bv = *reinterpret_cast<const float2*>(bias + col);
#pragma unroll
        for (int mt = 0; mt < 4; mt++) {
            int rowa = row0 + wm * 64 + mt * 16 + lq;
            int rowb = rowa + 8;
            if (rowa < M) {
                float2 o = make_float2(acc[mt][nt][0] + bv.x, acc[mt][nt][1] + bv.y);
                *reinterpret_cast<float2*>(C + (size_t)rowa * 256 + col) = o;
            }
            if (rowb < M) {
                float2 o = make_float2(acc[mt][nt][2] + bv.x, acc[mt][nt][3] + bv.y);
                *reinterpret_cast<float2*>(C + (size_t)rowb * 256 + col) = o;
            }
        }
    }
}

// ---------------- weight prep -------------------------------------------------
__global__ void transpose_W(const float* __restrict__ W, const float* __restrict__ b) {
    int idx = blockIdx.x * 256 + threadIdx.x;
    if (idx < 9 * 65536) {
        int w = idx >> 16;
        int rc = idx & 65535;
        int r = rc >> 8, c = rc & 255;
        float v = __uint_as_float(f2tf32(W[idx]));
        if (w < 6) g_Wt[(c_slot6[w] << 16) + (c << 8) + r] = v;
        else       g_Wcat[c * 768 + (w - 6) * 256 + r] = v;
    }
    if (idx < 6 * 256) {
        int w = idx >> 8;
        g_bias[(c_slot6[w] << 8) + (idx & 255)] = b[idx];
    }
    if (idx < 256) {
        g_bcat[idx] = b[6 * 256 + idx] + b[7 * 256 + idx] + b[8 * 256 + idx];
    }
}

// ---------------- stage 1: edge assemble + fused BN stats (set 1) -----------
__global__ void edge_assemble(float* __restrict__ epre, const int* __restrict__ src,
                              const int* __restrict__ dst, const int* __restrict__ gid)
{
    int t = blockIdx.x * blockDim.x + threadIdx.x;
    int q = t & 63;
    int stride = (gridDim.x * blockDim.x) >> 6;
    float s0 = 0.f, s1 = 0.f, s2 = 0.f, s3 = 0.f;
    float p0 = 0.f, p1 = 0.f, p2 = 0.f, p3 = 0.f;
    for (int e = t >> 6; e < NE; e += stride) {
        int s = src[e], d = dst[e];
        int g = gid[s];
        size_t off = (size_t)e * 256 + (q << 2);
        float4 v  = *reinterpret_cast<const float4*>(epre + off);
        float4 as = *reinterpret_cast<const float4*>(g_Ah + (size_t)s * 256 + (q << 2));
        float4 ad = *reinterpret_cast<const float4*>(g_Ah + (size_t)d * 256 + (q << 2));
        float4 cu = *reinterpret_cast<const float4*>(g_Cu + (size_t)g * 256 + (q << 2));
        v.x += as.x + ad.x + cu.x;
        v.y += as.y + ad.y + cu.y;
        v.z += as.z + ad.z + cu.z;
        v.w += as.w + ad.w + cu.w;
        *reinterpret_cast<float4*>(epre + off) = v;
        s0 += v.x; p0 += v.x * v.x;
        s1 += v.y; p1 += v.y * v.y;
        s2 += v.z; p2 += v.z * v.z;
        s3 += v.w; p3 += v.w * v.w;
    }
    int c = 256 + (q << 2);
    atomicAdd(&g_sumN[c + 0], (double)s0); atomicAdd(&g_sumsqN[c + 0], (double)p0);
    atomicAdd(&g_sumN[c + 1], (double)s1); atomicAdd(&g_sumsqN[c + 1], (double)p1);
    atomicAdd(&g_sumN[c + 2], (double)s2); atomicAdd(&g_sumsqN[c + 2], (double)p2);
    atomicAdd(&g_sumN[c + 3], (double)s3); atomicAdd(&g_sumsqN[c + 3], (double)p3);
}

// ---------------- BN finalize (restores stat zeros) --------------------------
__global__ void bn_finalize(int set, int M, const float* __restrict__ gam,
                            const float* __restrict__ bet)
{
    int c = threadIdx.x;
    double mean = g_sumN[set * 256 + c] / M;
    double var  = g_sumsqN[set * 256 + c] / M - mean * mean;
    g_sumN[set * 256 + c] = 0.0;
    g_sumsqN[set * 256 + c] = 0.0;
    float scale = gam[c] * rsqrtf((float)(var + 1e-5));
    g_bnA[c] = scale;
    g_bnB[c] = bet[c] - (float)mean * scale;
}

// ---------------- fused BN(e2)+relu + sigmoid/esum scatter + degG -----------
__global__ void bn_scatter_e2(float* __restrict__ e2, const int* __restrict__ src,
                              const int* __restrict__ dst, const int* __restrict__ gid)
{
    long long i = (long long)blockIdx.x * blockDim.x + threadIdx.x;
    if (i >= (long long)NE * 64) return;
    int e = (int)(i >> 6), q = (int)(i & 63);
    int c = q << 2;
    float4 sc = *reinterpret_cast<const float4*>(g_bnA + c);
    float4 bb = *reinterpret_cast<const float4*>(g_bnB + c);
    size_t off = (size_t)e * 256 + c;
    float4 v = *reinterpret_cast<const float4*>(e2 + off);
    v.x = fmaxf(v.x * sc.x + bb.x, 0.f);
    v.y = fmaxf(v.y * sc.y + bb.y, 0.f);
    v.z = fmaxf(v.z * sc.z + bb.z, 0.f);
    v.w = fmaxf(v.w * sc.w + bb.w, 0.f);
    *reinterpret_cast<float4*>(e2 + off) = v;
    int s = src[e], d = dst[e];
    float4 eh = *reinterpret_cast<const float4*>(g_Eh + (size_t)s * 256 + c);
    float g0 = 1.f / (1.f + __expf(-v.x));
    float g1 = 1.f / (1.f + __expf(-v.y));
    float g2 = 1.f / (1.f + __expf(-v.z));
    float g3 = 1.f / (1.f + __expf(-v.w));
    size_t doff = (size_t)d * 256 + c;
    red_add_v4(&g_num[doff], g0 * eh.x, g1 * eh.y, g2 * eh.z, g3 * eh.w);
    red_add_v4(&g_den[doff], g0, g1, g2, g3);
    red_add_v4(&g_esum[doff], v.x, v.y, v.z, v.w);
    if (q == 0) atomicAdd(&g_degG[gid[d]], 1.f);
}

// ---------------- stage 2: h2 assemble + stats set 0 (restores num/den) -----
__global__ void h2_assemble(float* __restrict__ h2, const int* __restrict__ gid)
{
    int t = blockIdx.x * blockDim.x + threadIdx.x;
    int q = t & 63;
    int stride = (gridDim.x * blockDim.x) >> 6;
    float s0 = 0.f, s1 = 0.f, s2 = 0.f, s3 = 0.f;
    float p0 = 0.f, p1 = 0.f, p2 = 0.f, p3 = 0.f;
    float4 z4 = make_float4(0.f, 0.f, 0.f, 0.f);
    for (int a = t >> 6; a < NA; a += stride) {
        int g = gid[a];
        size_t off = (size_t)a * 256 + (q << 2);
        float4 v  = *reinterpret_cast<const float4*>(h2 + off);
        float4 nu = *reinterpret_cast<const float4*>(g_num + off);
        float4 de = *reinterpret_cast<const float4*>(g_den + off);
        float4 fu = *reinterpret_cast<const float4*>(g_Fu + (size_t)g * 256 + (q << 2));
        *reinterpret_cast<float4*>(g_num + off) = z4;
        *reinterpret_cast<float4*>(g_den + off) = z4;
        v.x += nu.x / (de.x + 1e-6f) + fu.x;
        v.y += nu.y / (de.y + 1e-6f) + fu.y;
        v.z += nu.z / (de.z + 1e-6f) + fu.z;
        v.w += nu.w / (de.w + 1e-6f) + fu.w;
        *reinterpret_cast<float4*>(h2 + off) = v;
        s0 += v.x; p0 += v.x * v.x;
        s1 += v.y; p1 += v.y * v.y;
        s2 += v.z; p2 += v.z * v.z;
        s3 += v.w; p3 += v.w * v.w;
    }
    int c = q << 2;
    atomicAdd(&g_sumN[c + 0], (double)s0); atomicAdd(&g_sumsqN[c + 0], (double)p0);
    atomicAdd(&g_sumN[c + 1], (double)s1); atomicAdd(&g_sumsqN[c + 1], (double)p1);
    atomicAdd(&g_sumN[c + 2], (double)s2); atomicAdd(&g_sumsqN[c + 2], (double)p2);
    atomicAdd(&g_sumN[c + 3], (double)s3); atomicAdd(&g_sumsqN[c + 3], (double)p3);
}

// ---------------- BN apply h2 -------------------------------------------------
__global__ void bn_apply_h2(float* __restrict__ h2)
{
    long long i = (long long)blockIdx.x * blockDim.x + threadIdx.x;
    if (i >= (long long)NA * 64) return;
    int a = (int)(i >> 6), q = (int)(i & 63);
    int c = q << 2;
    float4 sc = *reinterpret_cast<const float4*>(g_bnA + c);
    float4 bb = *reinterpret_cast<const float4*>(g_bnB + c);
    size_t off = (size_t)a * 256 + c;
    float4 v = *reinterpret_cast<const float4*>(h2 + off);
    v.x = fmaxf(v.x * sc.x + bb.x, 0.f);
    v.y = fmaxf(v.y * sc.y + bb.y, 0.f);
    v.z = fmaxf(v.z * sc.z + bb.z, 0.f);
    v.w = fmaxf(v.w * sc.w + bb.w, 0.f);
    *reinterpret_cast<float4*>(h2 + off) = v;
}

// ---------------- stage 3: build A_cat (restores esum/degG zeros) ------------
__global__ void graph_collect(const float* __restrict__ h2, const float* __restrict__ u)
{
    int g = blockIdx.x;
    int c = threadIdx.x;
    int a0 = g * APG;
    float sh = 0.f, se = 0.f;
    for (int j = 0; j < APG; j++) {
        size_t off = (size_t)(a0 + j) * 256 + c;
        sh += h2[off];
        se += g_esum[off];
        g_esum[off] = 0.f;
    }
    __shared__ float sdeg;
    if (c == 0) { sdeg = g_degG[g]; g_degG[g] = 0.f; }
    __syncthreads();
    float invd = 1.f / sdeg;
    g_Acat[(size_t)g * 768 + c]       = sh * (1.f / APG);
    g_Acat[(size_t)g * 768 + 256 + c] = se * invd;
    g_Acat[(size_t)g * 768 + 512 + c] = u[(size_t)g * 256 + c];
}

// ---------------- BN stats (u2) + apply --------------------------------------
__global__ void bn_stats(const float* __restrict__ X, int M, int set)
{
    int c = threadIdx.x;
    int r0 = blockIdx.x * 256;
    int r1 = min(r0 + 256, M);
    float s = 0.f, s2 = 0.f;
    for (int r = r0; r < r1; r++) {
        float v = X[(size_t)r * 256 + c];
        s += v; s2 += v * v;
    }
    atomicAdd(&g_sumN[set * 256 + c], (double)s);
    atomicAdd(&g_sumsqN[set * 256 + c], (double)s2);
}

__global__ void bn_apply_u2(float* __restrict__ u2)
{
    int i = blockIdx.x * blockDim.x + threadIdx.x;
    if (i >= NG * 64) return;
    int a = i >> 6, q = i & 63;
    int c = q << 2;
    float4 sc = *reinterpret_cast<const float4*>(g_bnA + c);
    float4 bb = *reinterpret_cast<const float4*>(g_bnB + c);
    size_t off = (size_t)a * 256 + c;
    float4 v = *reinterpret_cast<const float4*>(u2 + off);
    v.x = fmaxf(v.x * sc.x + bb.x, 0.f);
    v.y = fmaxf(v.y * sc.y + bb.y, 0.f);
    v.z = fmaxf(v.z * sc.z + bb.z, 0.f);
    v.w = fmaxf(v.w * sc.w + bb.w, 0.f);
    *reinterpret_cast<float4*>(u2 + off) = v;
}

// ---------------- launch ------------------------------------------------------
extern "C" void kernel_launch(void* const* d_in, const int* in_sizes, int n_in,
                              void* d_out, int out_size)
{
    const float* h     = (const float*)d_in[0];
    const float* e     = (const float*)d_in[1];
    const float* u     = (const float*)d_in[2];
    const float* W     = (const float*)d_in[3];
    const float* b     = (const float*)d_in[4];
    const float* gamma = (const float*)d_in[5];
    const float* beta  = (const float*)d_in[6];
    const int*   src   = (const int*)d_in[7];
    const int*   dst   = (const int*)d_in[8];
    const int*   gid   = (const int*)d_in[9];

    float* out_h2 = (float*)d_out;
    float* out_e2 = out_h2 + (size_t)NA * 256;
    float* out_u2 = out_e2 + (size_t)NE * 256;

    float *pAh, *pEh, *pCu, *pFu, *pWt, *pBias, *pWcat, *pBcat, *pAcat;
    cudaGetSymbolAddress((void**)&pAh, g_Ah);
    cudaGetSymbolAddress((void**)&pEh, g_Eh);
    cudaGetSymbolAddress((void**)&pCu, g_Cu);
    cudaGetSymbolAddress((void**)&pFu, g_Fu);
    cudaGetSymbolAddress((void**)&pWt, g_Wt);
    cudaGetSymbolAddress((void**)&pBias, g_bias);
    cudaGetSymbolAddress((void**)&pWcat, g_Wcat);
    cudaGetSymbolAddress((void**)&pBcat, g_bcat);
    cudaGetSymbolAddress((void**)&pAcat, g_Acat);

    const int SMEM = 3 * 32768;   // 96 KB
    static int attr_done = 0;
    if (!attr_done) {
        cudaFuncSetAttribute(sgemm_tc, cudaFuncAttributeMaxDynamicSharedMemorySize, SMEM);
        attr_done = 1;
    }

    dim3 gH((NA + 127) / 128, 6);    // A,D,E on h
    dim3 gB((NE + 127) / 128, 2);    // B on e
    dim3 gUU((NG + 127) / 128, 4);   // C,F on u
    dim3 gCat((NG + 127) / 128, 2);  // concatenated stage-3 GEMM

    transpose_W<<<(9 * 65536 + 255) / 256, 256>>>(W, b);

    // ---- stage 1 + inputs of stage 2 ----
    sgemm_tc<<<gH, 256, SMEM>>>(h, pWt + 0 * 65536, pBias + 0 * 256,
                                pAh, out_h2, pEh, NA, 256);            // Ah, Dh, Eh
    sgemm_tc<<<gB, 256, SMEM>>>(e, pWt + 3 * 65536, pBias + 3 * 256,
                                out_e2, nullptr, nullptr, NE, 256);    // Be
    sgemm_tc<<<gUU, 256, SMEM>>>(u, pWt + 4 * 65536, pBias + 4 * 256,
                                 pCu, pFu, nullptr, NG, 256);          // Cu, Fu
    edge_assemble<<<1024, 256>>>(out_e2, src, dst, gid);               // + stats set1
    bn_finalize<<<1, 256>>>(1, NE, gamma + 256, beta + 256);
    bn_scatter_e2<<<(int)(((long long)NE * 64 + 255) / 256), 256>>>(out_e2, src, dst, gid);

    // ---- stage 2 ----
    h2_assemble<<<1024, 256>>>(out_h2, gid);                           // + stats set0
    bn_finalize<<<1, 256>>>(0, NA, gamma, beta);
    bn_apply_h2<<<(int)(((long long)NA * 64 + 255) / 256), 256>>>(out_h2);

    // ---- stage 3: linear-map sums then one K=768 GEMM ----
    graph_collect<<<NG, 256>>>(out_h2, u);
    sgemm_tc<<<gCat, 256, SMEM>>>(pAcat, pWcat, pBcat,
                                  out_u2, nullptr, nullptr, NG, 768);  // u2 pre-BN
    bn_stats<<<(NG + 255) / 256, 256>>>(out_u2, NG, 2);
    bn_finalize<<<1, 256>>>(2, NG, gamma + 512, beta + 512);
    bn_apply_u2<<<(NG * 64 + 255) / 256, 256>>>(out_u2);
}

// round 6
// speedup vs baseline: 3.5909x; 1.3935x over previous
#include <cuda_runtime.h>
#include <cstdint>
#include <math.h>

#define NA 80000
#define NE 250000
#define NG 2000
#define APG 40

// ---------------- device scratch (no allocation allowed) ---------------------
__device__ float g_Ah[NA * 256];
__device__ float g_Eh[NA * 256];
__device__ float g_Cu[NG * 256];
__device__ float g_Fu[NG * 256];
__device__ float g_num[NA * 256];     // zero-restored by h2_assemble
__device__ float g_den[NA * 256];     // zero-restored by h2_assemble
__device__ float g_esumG[NG * 256];   // per-graph e2 sums; zero-restored by graph_collect
__device__ float g_degG[NG];          // zero-restored by graph_collect
__device__ float g_Wt[6 * 256 * 256]; // slots 0..5, K-major [slot][n][k], tf32-rounded
__device__ float g_Wcat[256 * 768];   // [n][k0..767] = W6|W7|W8 K-major, tf32-rounded
__device__ float g_bias[6 * 256];
__device__ float g_bcat[256];         // b6+b7+b8
__device__ float g_Acat[NG * 768];    // [Sh/40 | Se/deg | u]
__device__ double g_sumB[8][768];     // banked stats; zero-restored by bn_finalize
__device__ double g_sumsqB[8][768];
__device__ float g_bnA[256];
__device__ float g_bnB[256];

// orig W idx -> slot:  W0->0(A) W1->3(B) W2->4(C) W3->1(D) W4->2(E) W5->5(F)
__constant__ int c_slot6[6] = {0, 3, 4, 1, 2, 5};

// ---------------- helpers -----------------------------------------------------
__device__ __forceinline__ uint32_t smem_u32(const void* p) {
    uint32_t a;
    asm("{ .reg .u64 t; cvta.to.shared.u64 t, %1; cvt.u32.u64 %0, t; }" : "=r"(a) : "l"(p));
    return a;
}
__device__ __forceinline__ uint32_t f2tf32(float v) {
    uint32_t u;
    asm("cvt.rna.tf32.f32 %0, %1;" : "=r"(u) : "f"(v));
    return u;
}
__device__ __forceinline__ void red_add_v4(float* addr, float a, float b, float c, float d) {
    asm volatile("red.global.add.v4.f32 [%0], {%1, %2, %3, %4};"
        :: "l"(addr), "f"(a), "f"(b), "f"(c), "f"(d) : "memory");
}

// ---------------- tf32 mma GEMM, 3-stage cp.async, swizzled smem -------------
// CTA tile 128x128. grid.y = 2*nSlots: w = y>>1 weight slot, half = y&1.
// If srcI != nullptr (edge-assemble mode, single slot): epilogue adds
// Ah[src]+Ah[dst]+Cu[gid[src]] and accumulates BN stats (set 1, banked).
__global__ void __launch_bounds__(256, 2) sgemm_tc(
    const float* __restrict__ A, const float* __restrict__ WtG,
    const float* __restrict__ biasG, float* __restrict__ C0,
    float* __restrict__ C1, float* __restrict__ C2, int M, int K,
    const int* __restrict__ srcI, const int* __restrict__ dstI,
    const int* __restrict__ gidI)
{
    extern __shared__ float sm[];
    const int tid  = threadIdx.x;
    const int lane = tid & 31;
    const int wid  = tid >> 5;
    const int wm   = wid & 1;
    const int wn   = wid >> 1;
    const int row0 = blockIdx.x * 128;
    const int w    = blockIdx.y >> 1;
    const int half = blockIdx.y & 1;
    const int col0 = half * 128;
    const int lq   = lane >> 2;
    const int lr   = lane & 3;

    const float* Wt   = WtG + (size_t)w * K * 256;
    const float* bias = biasG + w * 256;
    float* C = (w == 0) ? C0 : ((w == 1) ? C1 : C2);

    const uint32_t smbase = smem_u32(sm);
    const int chunks = K >> 5;

    auto load_chunk = [&](int c) {
        const int st = c % 3;
        const int k0 = c << 5;
        const uint32_t abase = smbase + st * 32768;
        const uint32_t bbase = abase + 16384;
#pragma unroll
        for (int ii = 0; ii < 4; ii++) {
            int i = tid + (ii << 8);
            int r = i >> 3, q = i & 7;
            int grow = row0 + r;
            const float* srcp = A + (size_t)grow * K + k0 + (q << 2);
            uint32_t dstA = abase + (uint32_t)((r << 5) + ((q ^ (r & 7)) << 2)) * 4;
            int sz = (grow < M) ? 16 : 0;
            asm volatile("cp.async.ca.shared.global [%0], [%1], 16, %2;"
                :: "r"(dstA), "l"(srcp), "r"(sz) : "memory");
        }
#pragma unroll
        for (int ii = 0; ii < 4; ii++) {
            int i = tid + (ii << 8);
            int n = i >> 3, q = i & 7;
            const float* srcp = Wt + (size_t)(col0 + n) * K + k0 + (q << 2);
            uint32_t dstB = bbase + (uint32_t)((n << 5) + ((q ^ (n & 7)) << 2)) * 4;
            asm volatile("cp.async.ca.shared.global [%0], [%1], 16;"
                :: "r"(dstB), "l"(srcp) : "memory");
        }
        asm volatile("cp.async.commit_group;" ::: "memory");
    };

    float acc[4][4][4];
#pragma unroll
    for (int i = 0; i < 4; i++)
#pragma unroll
        for (int j = 0; j < 4; j++)
#pragma unroll
            for (int r = 0; r < 4; r++) acc[i][j][r] = 0.f;

    load_chunk(0);
    if (chunks > 1) load_chunk(1);

    for (int c = 0; c < chunks; c++) {
        if (c + 1 < chunks) asm volatile("cp.async.wait_group 1;" ::: "memory");
        else                asm volatile("cp.async.wait_group 0;" ::: "memory");
        __syncthreads();
        if (c + 2 < chunks) load_chunk(c + 2);
        const float* sA = sm + (c % 3) * 8192;
        const float* sB = sA + 4096;

#pragma unroll
        for (int ks = 0; ks < 4; ks++) {
            const int s0 = (((2 * ks) ^ lq) << 2) + lr;
            const int s1 = (((2 * ks + 1) ^ lq) << 2) + lr;
            uint32_t bf[4][2];
#pragma unroll
            for (int nt = 0; nt < 4; nt++) {
                int n = wn * 32 + nt * 8 + lq;
                bf[nt][0] = __float_as_uint(sB[(n << 5) + s0]);
                bf[nt][1] = __float_as_uint(sB[(n << 5) + s1]);
            }
#pragma unroll
            for (int mt = 0; mt < 4; mt++) {
                int m = wm * 64 + mt * 16 + lq;
                uint32_t a0 = __float_as_uint(sA[(m << 5) + s0]);
                uint32_t a1 = __float_as_uint(sA[((m + 8) << 5) + s0]);
                uint32_t a2 = __float_as_uint(sA[(m << 5) + s1]);
                uint32_t a3 = __float_as_uint(sA[((m + 8) << 5) + s1]);
#pragma unroll
                for (int nt = 0; nt < 4; nt++) {
                    asm volatile(
                        "mma.sync.aligned.m16n8k8.row.col.f32.tf32.tf32.f32 "
                        "{%0,%1,%2,%3}, {%4,%5,%6,%7}, {%8,%9}, {%0,%1,%2,%3};"
                        : "+f"(acc[mt][nt][0]), "+f"(acc[mt][nt][1]),
                          "+f"(acc[mt][nt][2]), "+f"(acc[mt][nt][3])
                        : "r"(a0), "r"(a1), "r"(a2), "r"(a3),
                          "r"(bf[nt][0]), "r"(bf[nt][1]));
                }
            }
        }
    }

    if (srcI == nullptr) {
        // ---- plain epilogue ----
#pragma unroll
        for (int nt = 0; nt < 4; nt++) {
            int col = col0 + wn * 32 + nt * 8 + (lr << 1);
            float2 bv = *reinterpret_cast<const float2*>(bias + col);
#pragma unroll
            for (int mt = 0; mt < 4; mt++) {
                int rowa = row0 + wm * 64 + mt * 16 + lq;
                int rowb = rowa + 8;
                if (rowa < M) {
                    float2 o = make_float2(acc[mt][nt][0] + bv.x, acc[mt][nt][1] + bv.y);
                    *reinterpret_cast<float2*>(C + (size_t)rowa * 256 + col) = o;
                }
                if (rowb < M) {
                    float2 o = make_float2(acc[mt][nt][2] + bv.x, acc[mt][nt][3] + bv.y);
                    *reinterpret_cast<float2*>(C + (size_t)rowb * 256 + col) = o;
                }
            }
        }
    } else {
        // ---- edge-assemble epilogue: += Ah[src]+Ah[dst]+Cu[gid[src]], stats set1 ----
        float ss[4][2] = {{0.f,0.f},{0.f,0.f},{0.f,0.f},{0.f,0.f}};
        float sq[4][2] = {{0.f,0.f},{0.f,0.f},{0.f,0.f},{0.f,0.f}};
        float2 bvv[4];
#pragma unroll
        for (int nt = 0; nt < 4; nt++)
            bvv[nt] = *reinterpret_cast<const float2*>(bias + col0 + wn * 32 + nt * 8 + (lr << 1));
#pragma unroll
        for (int mt = 0; mt < 4; mt++) {
#pragma unroll
            for (int hr = 0; hr < 2; hr++) {
                int row = row0 + wm * 64 + mt * 16 + lq + hr * 8;
                if (row < M) {
                    int s = srcI[row], d = dstI[row];
                    int g = gidI[s];
                    const float* As_ = g_Ah + (size_t)s * 256;
                    const float* Ad_ = g_Ah + (size_t)d * 256;
                    const float* Cu_ = g_Cu + (size_t)g * 256;
#pragma unroll
                    for (int nt = 0; nt < 4; nt++) {
                        int col = col0 + wn * 32 + nt * 8 + (lr << 1);
                        float2 x1 = *reinterpret_cast<const float2*>(As_ + col);
                        float2 x2 = *reinterpret_cast<const float2*>(Ad_ + col);
                        float2 x3 = *reinterpret_cast<const float2*>(Cu_ + col);
                        float vx = acc[mt][nt][hr * 2 + 0] + bvv[nt].x + x1.x + x2.x + x3.x;
                        float vy = acc[mt][nt][hr * 2 + 1] + bvv[nt].y + x1.y + x2.y + x3.y;
                        *reinterpret_cast<float2*>(C + (size_t)row * 256 + col) =
                            make_float2(vx, vy);
                        ss[nt][0] += vx; sq[nt][0] += vx * vx;
                        ss[nt][1] += vy; sq[nt][1] += vy * vy;
                    }
                }
            }
        }
        int bank = blockIdx.x & 7;
#pragma unroll
        for (int nt = 0; nt < 4; nt++) {
#pragma unroll
            for (int j = 0; j < 2; j++) {
                float a = ss[nt][j], bq = sq[nt][j];
                a  += __shfl_xor_sync(0xffffffff, a, 4);
                bq += __shfl_xor_sync(0xffffffff, bq, 4);
                a  += __shfl_xor_sync(0xffffffff, a, 8);
                bq += __shfl_xor_sync(0xffffffff, bq, 8);
                a  += __shfl_xor_sync(0xffffffff, a, 16);
                bq += __shfl_xor_sync(0xffffffff, bq, 16);
                if (lq == 0) {
                    int col = col0 + wn * 32 + nt * 8 + (lr << 1) + j;
                    atomicAdd(&g_sumB[bank][256 + col], (double)a);
                    atomicAdd(&g_sumsqB[bank][256 + col], (double)bq);
                }
            }
        }
    }
}

// ---------------- weight prep -------------------------------------------------
__global__ void transpose_W(const float* __restrict__ W, const float* __restrict__ b) {
    int idx = blockIdx.x * 256 + threadIdx.x;
    if (idx < 9 * 65536) {
        int w = idx >> 16;
        int rc = idx & 65535;
        int r = rc >> 8, c = rc & 255;
        float v = __uint_as_float(f2tf32(W[idx]));
        if (w < 6) g_Wt[(c_slot6[w] << 16) + (c << 8) + r] = v;
        else       g_Wcat[c * 768 + (w - 6) * 256 + r] = v;
    }
    if (idx < 6 * 256) {
        int w = idx >> 8;
        g_bias[(c_slot6[w] << 8) + (idx & 255)] = b[idx];
    }
    if (idx < 256) {
        g_bcat[idx] = b[6 * 256 + idx] + b[7 * 256 + idx] + b[8 * 256 + idx];
    }
}

// ---------------- BN finalize (sums banks, restores zeros) -------------------
__global__ void bn_finalize(int set, int M, const float* __restrict__ gam,
                            const float* __restrict__ bet)
{
    int c = threadIdx.x;
    double s = 0.0, s2 = 0.0;
#pragma unroll
    for (int k = 0; k < 8; k++) {
        s  += g_sumB[k][set * 256 + c];
        s2 += g_sumsqB[k][set * 256 + c];
        g_sumB[k][set * 256 + c] = 0.0;
        g_sumsqB[k][set * 256 + c] = 0.0;
    }
    double mean = s / M;
    double var  = s2 / M - mean * mean;
    float scale = gam[c] * rsqrtf((float)(var + 1e-5));
    g_bnA[c] = scale;
    g_bnB[c] = bet[c] - (float)mean * scale;
}

// ---------------- fused BN(e2)+relu + sigmoid scatter + per-graph esum -------
__global__ void bn_scatter_e2(float* __restrict__ e2, const int* __restrict__ src,
                              const int* __restrict__ dst, const int* __restrict__ gid)
{
    long long i = (long long)blockIdx.x * blockDim.x + threadIdx.x;
    if (i >= (long long)NE * 64) return;
    int e = (int)(i >> 6), q = (int)(i & 63);
    int c = q << 2;
    float4 sc = *reinterpret_cast<const float4*>(g_bnA + c);
    float4 bb = *reinterpret_cast<const float4*>(g_bnB + c);
    size_t off = (size_t)e * 256 + c;
    float4 v = *reinterpret_cast<const float4*>(e2 + off);
    v.x = fmaxf(v.x * sc.x + bb.x, 0.f);
    v.y = fmaxf(v.y * sc.y + bb.y, 0.f);
    v.z = fmaxf(v.z * sc.z + bb.z, 0.f);
    v.w = fmaxf(v.w * sc.w + bb.w, 0.f);
    *reinterpret_cast<float4*>(e2 + off) = v;
    int s = src[e], d = dst[e];
    int gd = gid[d];
    float4 eh = *reinterpret_cast<const float4*>(g_Eh + (size_t)s * 256 + c);
    float g0 = 1.f / (1.f + __expf(-v.x));
    float g1 = 1.f / (1.f + __expf(-v.y));
    float g2 = 1.f / (1.f + __expf(-v.z));
    float g3 = 1.f / (1.f + __expf(-v.w));
    size_t doff = (size_t)d * 256 + c;
    red_add_v4(&g_num[doff], g0 * eh.x, g1 * eh.y, g2 * eh.z, g3 * eh.w);
    red_add_v4(&g_den[doff], g0, g1, g2, g3);
    red_add_v4(&g_esumG[(size_t)gd * 256 + c], v.x, v.y, v.z, v.w);
    if (q == 0) atomicAdd(&g_degG[gd], 1.f);
}

// ---------------- stage 2: h2 assemble + stats set 0 (restores num/den) -----
__global__ void h2_assemble(float* __restrict__ h2, const int* __restrict__ gid)
{
    int t = blockIdx.x * blockDim.x + threadIdx.x;
    int q = t & 63;
    int stride = (gridDim.x * blockDim.x) >> 6;
    float s0 = 0.f, s1 = 0.f, s2 = 0.f, s3 = 0.f;
    float p0 = 0.f, p1 = 0.f, p2 = 0.f, p3 = 0.f;
    float4 z4 = make_float4(0.f, 0.f, 0.f, 0.f);
    for (int a = t >> 6; a < NA; a += stride) {
        int g = gid[a];
        size_t off = (size_t)a * 256 + (q << 2);
        float4 v  = *reinterpret_cast<const float4*>(h2 + off);
        float4 nu = *reinterpret_cast<const float4*>(g_num + off);
        float4 de = *reinterpret_cast<const float4*>(g_den + off);
        float4 fu = *reinterpret_cast<const float4*>(g_Fu + (size_t)g * 256 + (q << 2));
        *reinterpret_cast<float4*>(g_num + off) = z4;
        *reinterpret_cast<float4*>(g_den + off) = z4;
        v.x += nu.x / (de.x + 1e-6f) + fu.x;
        v.y += nu.y / (de.y + 1e-6f) + fu.y;
        v.z += nu.z / (de.z + 1e-6f) + fu.z;
        v.w += nu.w / (de.w + 1e-6f) + fu.w;
        *reinterpret_cast<float4*>(h2 + off) = v;
        s0 += v.x; p0 += v.x * v.x;
        s1 += v.y; p1 += v.y * v.y;
        s2 += v.z; p2 += v.z * v.z;
        s3 += v.w; p3 += v.w * v.w;
    }
    int bank = blockIdx.x & 7;
    int c = q << 2;
    atomicAdd(&g_sumB[bank][c + 0], (double)s0); atomicAdd(&g_sumsqB[bank][c + 0], (double)p0);
    atomicAdd(&g_sumB[bank][c + 1], (double)s1); atomicAdd(&g_sumsqB[bank][c + 1], (double)p1);
    atomicAdd(&g_sumB[bank][c + 2], (double)s2); atomicAdd(&g_sumsqB[bank][c + 2], (double)p2);
    atomicAdd(&g_sumB[bank][c + 3], (double)s3); atomicAdd(&g_sumsqB[bank][c + 3], (double)p3);
}

// ------- stage 3: BN-apply h2 + per-graph sums + A_cat (restores zeros) ------
__global__ void graph_collect(float* __restrict__ h2, const float* __restrict__ u)
{
    int g = blockIdx.x;
    int c = threadIdx.x;
    float scA = g_bnA[c], scB = g_bnB[c];
    int a0 = g * APG;
    float sh = 0.f;
    for (int j = 0; j < APG; j++) {
        size_t off = (size_t)(a0 + j) * 256 + c;
        float v = h2[off];
        v = fmaxf(v * scA + scB, 0.f);
        h2[off] = v;
        sh += v;
    }
    float se = g_esumG[(size_t)g * 256 + c];
    g_esumG[(size_t)g * 256 + c] = 0.f;
    __shared__ float sdeg;
    if (c == 0) { sdeg = g_degG[g]; g_degG[g] = 0.f; }
    __syncthreads();
    float invd = 1.f / sdeg;
    g_Acat[(size_t)g * 768 + c]       = sh * (1.f / APG);
    g_Acat[(size_t)g * 768 + 256 + c] = se * invd;
    g_Acat[(size_t)g * 768 + 512 + c] = u[(size_t)g * 256 + c];
}

// ---------------- BN stats (u2) + apply --------------------------------------
__global__ void bn_stats(const float* __restrict__ X, int M, int set)
{
    int c = threadIdx.x;
    int r0 = blockIdx.x * 256;
    int r1 = min(r0 + 256, M);
    float s = 0.f, s2 = 0.f;
    for (int r = r0; r < r1; r++) {
        float v = X[(size_t)r * 256 + c];
        s += v; s2 += v * v;
    }
    int bank = blockIdx.x & 7;
    atomicAdd(&g_sumB[bank][set * 256 + c], (double)s);
    atomicAdd(&g_sumsqB[bank][set * 256 + c], (double)s2);
}

__global__ void bn_apply_u2(float* __restrict__ u2)
{
    int i = blockIdx.x * blockDim.x + threadIdx.x;
    if (i >= NG * 64) return;
    int a = i >> 6, q = i & 63;
    int c = q << 2;
    float4 sc = *reinterpret_cast<const float4*>(g_bnA + c);
    float4 bb = *reinterpret_cast<const float4*>(g_bnB + c);
    size_t off = (size_t)a * 256 + c;
    float4 v = *reinterpret_cast<const float4*>(u2 + off);
    v.x = fmaxf(v.x * sc.x + bb.x, 0.f);
    v.y = fmaxf(v.y * sc.y + bb.y, 0.f);
    v.z = fmaxf(v.z * sc.z + bb.z, 0.f);
    v.w = fmaxf(v.w * sc.w + bb.w, 0.f);
    *reinterpret_cast<float4*>(u2 + off) = v;
}

// ---------------- launch ------------------------------------------------------
extern "C" void kernel_launch(void* const* d_in, const int* in_sizes, int n_in,
                              void* d_out, int out_size)
{
    const float* h     = (const float*)d_in[0];
    const float* e     = (const float*)d_in[1];
    const float* u     = (const float*)d_in[2];
    const float* W     = (const float*)d_in[3];
    const float* b     = (const float*)d_in[4];
    const float* gamma = (const float*)d_in[5];
    const float* beta  = (const float*)d_in[6];
    const int*   src   = (const int*)d_in[7];
    const int*   dst   = (const int*)d_in[8];
    const int*   gid   = (const int*)d_in[9];

    float* out_h2 = (float*)d_out;
    float* out_e2 = out_h2 + (size_t)NA * 256;
    float* out_u2 = out_e2 + (size_t)NE * 256;

    float *pAh, *pEh, *pCu, *pFu, *pWt, *pBias, *pWcat, *pBcat, *pAcat;
    cudaGetSymbolAddress((void**)&pAh, g_Ah);
    cudaGetSymbolAddress((void**)&pEh, g_Eh);
    cudaGetSymbolAddress((void**)&pCu, g_Cu);
    cudaGetSymbolAddress((void**)&pFu, g_Fu);
    cudaGetSymbolAddress((void**)&pWt, g_Wt);
    cudaGetSymbolAddress((void**)&pBias, g_bias);
    cudaGetSymbolAddress((void**)&pWcat, g_Wcat);
    cudaGetSymbolAddress((void**)&pBcat, g_bcat);
    cudaGetSymbolAddress((void**)&pAcat, g_Acat);

    const int SMEM = 3 * 32768;   // 96 KB
    static int attr_done = 0;
    if (!attr_done) {
        cudaFuncSetAttribute(sgemm_tc, cudaFuncAttributeMaxDynamicSharedMemorySize, SMEM);
        attr_done = 1;
    }

    dim3 gH((NA + 127) / 128, 6);    // A,D,E on h
    dim3 gB((NE + 127) / 128, 2);    // B on e (+ edge assemble epilogue)
    dim3 gUU((NG + 127) / 128, 4);   // C,F on u
    dim3 gCat((NG + 127) / 128, 2);  // concatenated stage-3 GEMM

    transpose_W<<<(9 * 65536 + 255) / 256, 256>>>(W, b);

    // ---- stage 1 (+ stage-2 GEMM inputs) ----
    sgemm_tc<<<gH, 256, SMEM>>>(h, pWt + 0 * 65536, pBias + 0 * 256,
                                pAh, out_h2, pEh, NA, 256,
                                nullptr, nullptr, nullptr);            // Ah, Dh, Eh
    sgemm_tc<<<gUU, 256, SMEM>>>(u, pWt + 4 * 65536, pBias + 4 * 256,
                                 pCu, pFu, nullptr, NG, 256,
                                 nullptr, nullptr, nullptr);           // Cu, Fu
    sgemm_tc<<<gB, 256, SMEM>>>(e, pWt + 3 * 65536, pBias + 3 * 256,
                                out_e2, nullptr, nullptr, NE, 256,
                                src, dst, gid);                        // Be + assemble + stats1
    bn_finalize<<<1, 256>>>(1, NE, gamma + 256, beta + 256);
    bn_scatter_e2<<<(int)(((long long)NE * 64 + 255) / 256), 256>>>(out_e2, src, dst, gid);

    // ---- stage 2 ----
    h2_assemble<<<1024, 256>>>(out_h2, gid);                           // + stats set0
    bn_finalize<<<1, 256>>>(0, NA, gamma, beta);

    // ---- stage 3 ----
    graph_collect<<<NG, 256>>>(out_h2, u);                             // BN-apply h2 + A_cat
    sgemm_tc<<<gCat, 256, SMEM>>>(pAcat, pWcat, pBcat,
                                  out_u2, nullptr, nullptr, NG, 768,
                                  nullptr, nullptr, nullptr);          // u2 pre-BN
    bn_stats<<<(NG + 255) / 256, 256>>>(out_u2, NG, 2);
    bn_finalize<<<1, 256>>>(2, NG, gamma + 512, beta + 512);
    bn_apply_u2<<<(NG * 64 + 255) / 256, 256>>>(out_u2);
}